// round 14
// baseline (speedup 1.0000x reference)
#include <cuda_runtime.h>
#include <cuda_fp16.h>
#include <math.h>
#include <stdint.h>

#define NN    100000
#define NE    1600000
#define D_INF 128
#define D_H   256
#define D_O   40
#define SCAN_BLOCKS ((NN + 1023) / 1024)

// ---------------- scratch (device globals; no allocation allowed) ----------
__device__ __align__(256) __half g_bufHA[(size_t)NN * D_H];
__device__ __align__(256) __half g_bufHB[(size_t)NN * D_H];
__device__ int   g_deg[NN];          // zeroed by csr_x_kernel of previous replay (zero-init first run)
__device__ float g_dinv[NN];
__device__ int   g_rowptr[NN + 1];
__device__ int   g_cursor[NN];
__device__ int   g_col[NE];
__device__ int   g_bsum[256];
__device__ float g_sumA[4 * 256];    // per-layer BN stats slots
__device__ float g_sumsqA[4 * 256];
__device__ __align__(256) __half g_w0[256 * 128];
__device__ __align__(256) __half g_wh[3 * 256 * 256];
__device__ __align__(256) __half g_wl[64 * 256];

// ---------------- helpers ----------------------------------------------------
__device__ __forceinline__ uint32_t smem_u32(const void* p) {
    uint32_t a;
    asm("{ .reg .u64 t; cvta.to.shared.u64 t, %1; cvt.u32.u64 %0, t; }" : "=r"(a) : "l"(p));
    return a;
}
#define SW128(o) ((o) ^ (((o) >> 3) & 0x70))

__device__ __forceinline__ void ldm_x4(uint32_t* r, uint32_t addr) {
    asm volatile("ldmatrix.sync.aligned.m8n8.x4.shared.b16 {%0,%1,%2,%3}, [%4];"
                 : "=r"(r[0]), "=r"(r[1]), "=r"(r[2]), "=r"(r[3]) : "r"(addr));
}
__device__ __forceinline__ void mma_f16(float* c, const uint32_t* a, uint32_t b0, uint32_t b1) {
    asm volatile(
        "mma.sync.aligned.m16n8k16.row.col.f32.f16.f16.f32 "
        "{%0,%1,%2,%3}, {%4,%5,%6,%7}, {%8,%9}, {%0,%1,%2,%3};"
        : "+f"(c[0]), "+f"(c[1]), "+f"(c[2]), "+f"(c[3])
        : "r"(a[0]), "r"(a[1]), "r"(a[2]), "r"(a[3]), "r"(b0), "r"(b1));
}
__device__ __forceinline__ void cp16(uint32_t dst, const void* src) {
    asm volatile("cp.async.cg.shared.global [%0], [%1], 16;" :: "r"(dst), "l"(src));
}
#define CP_COMMIT() asm volatile("cp.async.commit_group;" ::: "memory")
#define CP_WAIT0()  asm volatile("cp.async.wait_group 0;" ::: "memory")

// ---------------- prep: weight convert + degree count + stats zero ----------
#define CVT_TOTAL (32768 + 196608 + 16384)
__global__ void prep_kernel(const float* __restrict__ W0,
                            const float* __restrict__ Wh,
                            const float* __restrict__ Wl,
                            const int* __restrict__ rowE) {
    int i = blockIdx.x * 256 + threadIdx.x;
    if (i < NE) atomicAdd(&g_deg[rowE[i]], 1);
    if (i < 1024) { g_sumA[i] = 0.f; g_sumsqA[i] = 0.f; }
    if (i < 32768) {
        int n = i >> 7, k = i & 127;
        g_w0[i] = __float2half_rn(W0[k * 256 + n]);
    } else if (i < 229376) {
        int j = i - 32768;
        int l = j >> 16, r = j & 65535;
        int n = r >> 8, k = r & 255;
        g_wh[j] = __float2half_rn(Wh[l * 65536 + k * 256 + n]);
    } else if (i < CVT_TOTAL) {
        int j = i - 229376;
        int n = j >> 8, k = j & 255;
        g_wl[j] = __float2half_rn((n < D_O) ? Wl[k * D_O + n] : 0.f);
    }
}

// ---------------- scans ------------------------------------------------------
__global__ void scan1_kernel() {
    __shared__ int sm[1024];
    int tid = threadIdx.x;
    int i = blockIdx.x * 1024 + tid;
    int v = (i < NN) ? g_deg[i] : 0;
    int x = v;
    sm[tid] = x;
    __syncthreads();
    #pragma unroll
    for (int off = 1; off < 1024; off <<= 1) {
        int t = (tid >= off) ? sm[tid - off] : 0;
        __syncthreads();
        x += t;
        sm[tid] = x;
        __syncthreads();
    }
    if (i < NN) g_rowptr[i] = x - v;
    if (tid == 1023) g_bsum[blockIdx.x] = x;
}
__global__ void scan2_kernel() {
    __shared__ int sm[128];
    int tid = threadIdx.x;
    int v = (tid < SCAN_BLOCKS) ? g_bsum[tid] : 0;
    int x = v;
    sm[tid] = x;
    __syncthreads();
    #pragma unroll
    for (int off = 1; off < 128; off <<= 1) {
        int t = (tid >= off) ? sm[tid - off] : 0;
        __syncthreads();
        x += t;
        sm[tid] = x;
        __syncthreads();
    }
    if (tid < SCAN_BLOCKS) g_bsum[tid] = x - v;
    if (tid == 127) g_rowptr[NN] = x;
}
__global__ void scan3_kernel() {
    int i = blockIdx.x * blockDim.x + threadIdx.x;
    if (i >= NN) return;
    int rp = g_rowptr[i] + g_bsum[i >> 10];
    g_rowptr[i] = rp;
    g_cursor[i] = rp;
    g_dinv[i] = rsqrtf((float)(g_deg[i] + 1));
}

// ---------------- CSR fill + x->fp16*dinv + deg reset (one launch) ----------
__global__ void csr_x_kernel(const int* __restrict__ rowE, const int* __restrict__ colE,
                             const float* __restrict__ x, __half* __restrict__ xh) {
    int i = blockIdx.x * 256 + threadIdx.x;     // 0 .. NN*32 (3.2M)
    if (i < NE) {
        int p = atomicAdd(&g_cursor[rowE[i]], 1);
        g_col[p] = colE[i];
    }
    if (i < NN) g_deg[i] = 0;                   // reset for next replay
    if (i < NN * 32) {                          // float4 index
        int row = i >> 5;
        float d = g_dinv[row];
        float4 v = reinterpret_cast<const float4*>(x)[i];
        __half2 a = __floats2half2_rn(v.x * d, v.y * d);
        __half2 b = __floats2half2_rn(v.z * d, v.w * d);
        uint2 u;
        u.x = *reinterpret_cast<uint32_t*>(&a);
        u.y = *reinterpret_cast<uint32_t*>(&b);
        reinterpret_cast<uint2*>(xh)[i] = u;
    }
}

// ---------------- pipelined warp-MMA single-product fp16 GEMM (PDL) ---------
template <int KTOT, int NT, bool BN, bool SCALE, bool STATS>
__global__ __launch_bounds__(512)
void gemm_mma_kernel(const __half* __restrict__ A,
                     const __half* __restrict__ W,
                     __half* __restrict__ C,
                     const float* __restrict__ statsS,
                     const float* __restrict__ statsQ,
                     const float* __restrict__ gamma,
                     const float* __restrict__ beta,
                     float* __restrict__ outS,
                     float* __restrict__ outQ) {
    constexpr int OF_B = 16384;               // A: 128 rows x 128B
    constexpr int STG = 16384 + NT * 128;
    constexpr int NPW = NT / 4;
    constexpr int NI = NPW / 8;
    constexpr int KCH = KTOT / 64;

    extern __shared__ __align__(1024) char smem[];
    __shared__ float s_scale[256];
    __shared__ float s_shift[256];
    uint32_t sb = smem_u32(smem);
    int tid = threadIdx.x, lane = tid & 31, wid = tid >> 5;
    int wm = wid >> 2, wn = wid & 3;
    int rowBase = blockIdx.x * 128;

    int cg = (tid & 7) * 8;
    int rr = tid >> 3;
    uint4 av[2];

    auto cpB = [&](int ch, int s) {
        int k0 = ch * 64;
        uint32_t base = sb + s * STG;
        #pragma unroll
        for (int p = 0; p < NT / 64; ++p) {
            int n = rr + p * 64;
            size_t go = (size_t)n * KTOT + k0 + cg;
            uint32_t off = SW128((uint32_t)(n * 128 + cg * 2));
            cp16(base + OF_B + off, W + go);
        }
    };

    // ---- PDL prologue: W is constant (written by prep, long complete) ----
    cpB(0, 0);
    cudaGridDependencySynchronize();

    if (BN) {
        if (tid < 256) {
            float s = statsS[tid];
            float q = statsQ[tid];
            float mu = s * (1.f / NN);
            float var = q * (1.f / NN) - mu * mu;
            float sc = rsqrtf(var + 1e-5f) * gamma[tid];
            s_scale[tid] = sc;
            s_shift[tid] = beta[tid] - mu * sc;
        }
        __syncthreads();
    }

    float acc[2][NI][4];
    #pragma unroll
    for (int mi = 0; mi < 2; ++mi)
        #pragma unroll
        for (int ni = 0; ni < NI; ++ni)
            #pragma unroll
            for (int q = 0; q < 4; ++q) acc[mi][ni][q] = 0.f;

    auto ldgA = [&](int ch) {
        int k0 = ch * 64;
        #pragma unroll
        for (int p = 0; p < 2; ++p) {
            int gr = rowBase + rr + p * 64;
            if (gr < NN)
                av[p] = *reinterpret_cast<const uint4*>(A + (size_t)gr * KTOT + k0 + cg);
            else
                av[p] = make_uint4(0, 0, 0, 0);
        }
    };
    auto stsA = [&](int ch, int s) {
        int k0 = ch * 64;
        char* base = smem + s * STG;
        #pragma unroll
        for (int p = 0; p < 2; ++p) {
            __half2* hp = reinterpret_cast<__half2*>(&av[p]);
            uint4 o;
            __half2* op = reinterpret_cast<__half2*>(&o);
            #pragma unroll
            for (int j = 0; j < 4; ++j) {
                float2 f = __half22float2(hp[j]);
                int c = k0 + cg + j * 2;
                f.x = fmaxf(fmaf(f.x, s_scale[c], s_shift[c]), 0.f);
                f.y = fmaxf(fmaf(f.y, s_scale[c + 1], s_shift[c + 1]), 0.f);
                op[j] = __floats2half2_rn(f.x, f.y);
            }
            uint32_t off = SW128((uint32_t)((rr + p * 64) * 128 + cg * 2));
            *reinterpret_cast<uint4*>(base + off) = o;
        }
    };
    auto cpA = [&](int ch, int s) {
        int k0 = ch * 64;
        uint32_t base = sb + s * STG;
        #pragma unroll
        for (int p = 0; p < 2; ++p) {
            int gr = rowBase + rr + p * 64;
            uint32_t off = SW128((uint32_t)((rr + p * 64) * 128 + cg * 2));
            if (gr < NN)
                cp16(base + off, A + (size_t)gr * KTOT + k0 + cg);
            else
                *reinterpret_cast<uint4*>(smem + s * STG + off) = make_uint4(0, 0, 0, 0);
        }
    };
    auto domma = [&](int s) {
        uint32_t aF = sb + s * STG;
        uint32_t bF = aF + OF_B;
        #pragma unroll
        for (int ks = 0; ks < 4; ++ks) {
            int kk = ks * 16;
            uint32_t af[2][4];
            #pragma unroll
            for (int mi = 0; mi < 2; ++mi) {
                int r = wm * 32 + mi * 16 + (lane & 15);
                int c = kk + (lane >> 4) * 8;
                uint32_t off = SW128((uint32_t)(r * 128 + c * 2));
                ldm_x4(af[mi], aF + off);
            }
            #pragma unroll
            for (int nt = 0; nt < NI / 2; ++nt) {
                int g = lane >> 3;
                int row = wn * NPW + nt * 16 + (g >> 1) * 8 + (lane & 7);
                int c = kk + (g & 1) * 8;
                uint32_t off = SW128((uint32_t)(row * 128 + c * 2));
                uint32_t bh[4];
                ldm_x4(bh, bF + off);
                #pragma unroll
                for (int half = 0; half < 2; ++half) {
                    int ni = nt * 2 + half;
                    #pragma unroll
                    for (int mi = 0; mi < 2; ++mi)
                        mma_f16(acc[mi][ni], af[mi], bh[half * 2], bh[half * 2 + 1]);
                }
            }
        }
    };

    if (BN) ldgA(0); else cpA(0, 0);
    CP_COMMIT();
    if (BN) stsA(0, 0);

    for (int ch = 0; ch < KCH; ++ch) {
        int s = ch & 1;
        CP_WAIT0();
        __syncthreads();
        if (ch + 1 < KCH) {
            if (BN) ldgA(ch + 1); else cpA(ch + 1, s ^ 1);
            cpB(ch + 1, s ^ 1);
            CP_COMMIT();
        }
        domma(s);
        if (BN && ch + 1 < KCH) stsA(ch + 1, s ^ 1);
    }

    // epilogue: fp16 store (x dinv if SCALE)
    #pragma unroll
    for (int mi = 0; mi < 2; ++mi) {
        int r0 = rowBase + wm * 32 + mi * 16 + (lane >> 2);
        int r1 = r0 + 8;
        float d0 = 1.f, d1 = 1.f;
        if (SCALE) {
            d0 = (r0 < NN) ? g_dinv[r0] : 0.f;
            d1 = (r1 < NN) ? g_dinv[r1] : 0.f;
        }
        #pragma unroll
        for (int ni = 0; ni < NI; ++ni) {
            int c0 = wn * NPW + ni * 8 + (lane & 3) * 2;
            if (r0 < NN)
                *reinterpret_cast<__half2*>(C + (size_t)r0 * NT + c0) =
                    __floats2half2_rn(acc[mi][ni][0] * d0, acc[mi][ni][1] * d0);
            if (r1 < NN)
                *reinterpret_cast<__half2*>(C + (size_t)r1 * NT + c0) =
                    __floats2half2_rn(acc[mi][ni][2] * d1, acc[mi][ni][3] * d1);
        }
    }

    // fused BN stats (layer-0 GEMM): fp32 accumulators, padding rows are zero
    if constexpr (STATS) {
        __shared__ float s_sum[256];
        __shared__ float s_sq[256];
        if (tid < 256) { s_sum[tid] = 0.f; s_sq[tid] = 0.f; }
        __syncthreads();
        #pragma unroll
        for (int ni = 0; ni < NI; ++ni) {
            float s0 = 0.f, q0 = 0.f, s1 = 0.f, q1 = 0.f;
            #pragma unroll
            for (int mi = 0; mi < 2; ++mi) {
                float va = acc[mi][ni][0], vb = acc[mi][ni][2];
                s0 += va + vb; q0 += va * va + vb * vb;
                float vc = acc[mi][ni][1], vd = acc[mi][ni][3];
                s1 += vc + vd; q1 += vc * vc + vd * vd;
            }
            #pragma unroll
            for (int off = 4; off <= 16; off <<= 1) {
                s0 += __shfl_xor_sync(0xffffffffu, s0, off);
                q0 += __shfl_xor_sync(0xffffffffu, q0, off);
                s1 += __shfl_xor_sync(0xffffffffu, s1, off);
                q1 += __shfl_xor_sync(0xffffffffu, q1, off);
            }
            if ((lane >> 2) == 0) {
                int c0 = wn * NPW + ni * 8 + (lane & 3) * 2;
                atomicAdd(&s_sum[c0], s0);
                atomicAdd(&s_sq[c0], q0);
                atomicAdd(&s_sum[c0 + 1], s1);
                atomicAdd(&s_sq[c0 + 1], q1);
            }
        }
        __syncthreads();
        if (tid < 256) {
            atomicAdd(&outS[tid], s_sum[tid]);
            atomicAdd(&outQ[tid], s_sq[tid]);
        }
    }
}

// ---------------- SpMM fp16 -> fp16, TWO rows per warp (dual MLP chains) ----
// Block: 16 warps x 2 rows = 32 rows. Stats: sum of both rows per column.
template <bool STATS, int COLS>
__global__ __launch_bounds__(512)
void spmmh_kernel(const __half* __restrict__ in, __half* __restrict__ out,
                  float* __restrict__ outS, float* __restrict__ outQ) {
    constexpr int CPL = COLS / 32;
    int warp = threadIdx.x >> 5, lane = threadIdx.x & 31;
    int row0 = blockIdx.x * 32 + warp * 2;
    int row1 = row0 + 1;

    int s0 = g_rowptr[row0], e0 = g_rowptr[row0 + 1];
    int s1 = g_rowptr[row1], e1 = g_rowptr[row1 + 1];
    float d0 = g_dinv[row0];
    float d1 = g_dinv[row1];
    cudaGridDependencySynchronize();

    float acc0[CPL], acc1[CPL];
    {
        const __half2* p0 = reinterpret_cast<const __half2*>(in + (size_t)row0 * COLS + lane * CPL);
        const __half2* p1 = reinterpret_cast<const __half2*>(in + (size_t)row1 * COLS + lane * CPL);
        #pragma unroll
        for (int j = 0; j < CPL / 2; ++j) {
            float2 f0 = __half22float2(p0[j]);
            float2 f1 = __half22float2(p1[j]);
            acc0[j * 2] = f0.x; acc0[j * 2 + 1] = f0.y;
            acc1[j * 2] = f1.x; acc1[j * 2 + 1] = f1.y;
        }
    }

    auto gather = [&](int c, float* acc) {
        const __half* p = in + (size_t)c * COLS + lane * CPL;
        if constexpr (CPL == 8) {
            uint4 u = *reinterpret_cast<const uint4*>(p);
            __half2* hp = reinterpret_cast<__half2*>(&u);
            #pragma unroll
            for (int j = 0; j < 4; ++j) {
                float2 f = __half22float2(hp[j]);
                acc[j * 2] += f.x;
                acc[j * 2 + 1] += f.y;
            }
        } else {
            uint2 u = *reinterpret_cast<const uint2*>(p);
            __half2* hp = reinterpret_cast<__half2*>(&u);
            #pragma unroll
            for (int j = 0; j < 2; ++j) {
                float2 f = __half22float2(hp[j]);
                acc[j * 2] += f.x;
                acc[j * 2 + 1] += f.y;
            }
        }
    };

    int i0 = s0, i1 = s1;
    while (i0 < e0 && i1 < e1) {          // dual independent chains
        int c0 = g_col[i0++];
        int c1 = g_col[i1++];
        gather(c0, acc0);
        gather(c1, acc1);
    }
    while (i0 < e0) gather(g_col[i0++], acc0);
    while (i1 < e1) gather(g_col[i1++], acc1);

    #pragma unroll
    for (int j = 0; j < CPL; ++j) { acc0[j] *= d0; acc1[j] *= d1; }

    {
        __half2 o0[CPL / 2], o1[CPL / 2];
        #pragma unroll
        for (int j = 0; j < CPL / 2; ++j) {
            o0[j] = __floats2half2_rn(acc0[j * 2], acc0[j * 2 + 1]);
            o1[j] = __floats2half2_rn(acc1[j * 2], acc1[j * 2 + 1]);
        }
        __half* op0 = out + (size_t)row0 * COLS + lane * CPL;
        __half* op1 = out + (size_t)row1 * COLS + lane * CPL;
        if constexpr (CPL == 8) {
            *reinterpret_cast<uint4*>(op0) = *reinterpret_cast<uint4*>(o0);
            *reinterpret_cast<uint4*>(op1) = *reinterpret_cast<uint4*>(o1);
        } else {
            *reinterpret_cast<uint2*>(op0) = *reinterpret_cast<uint2*>(o0);
            *reinterpret_cast<uint2*>(op1) = *reinterpret_cast<uint2*>(o1);
        }
    }

    if constexpr (STATS) {
        __shared__ float ss[16][COLS];
        __shared__ float sq[16][COLS];
        #pragma unroll
        for (int j = 0; j < CPL; ++j) {
            ss[warp][lane * CPL + j] = acc0[j] + acc1[j];
            sq[warp][lane * CPL + j] = acc0[j] * acc0[j] + acc1[j] * acc1[j];
        }
        __syncthreads();
        int t = threadIdx.x;
        if (t < COLS) {
            float sm = 0.f;
            #pragma unroll
            for (int w = 0; w < 16; ++w) sm += ss[w][t];
            atomicAdd(&outS[t], sm);
        } else if (t < 2 * COLS) {
            int c = t - COLS;
            float sm = 0.f;
            #pragma unroll
            for (int w = 0; w < 16; ++w) sm += sq[w][c];
            atomicAdd(&outQ[c], sm);
        }
    }
}

// ---------------- final SpMM (64-stride fp16 in) + log_softmax, PDL ---------
__global__ __launch_bounds__(256)
void spmm40_softmax_kernel(const __half* __restrict__ hs,
                           const float* __restrict__ bl,
                           float* __restrict__ out) {
    int warp = threadIdx.x >> 5, lane = threadIdx.x & 31;
    int row = blockIdx.x * 8 + warp;
    int s = 0, e = 0;
    float d = 0.f;
    if (row < NN) {
        s = g_rowptr[row];
        e = g_rowptr[row + 1];
        d = g_dinv[row];
    }
    cudaGridDependencySynchronize();
    if (row >= NN) return;

    size_t rbase = (size_t)row * 64;
    float a0 = __half2float(hs[rbase + lane]);
    float a1 = (lane < 8) ? __half2float(hs[rbase + 32 + lane]) : 0.f;
    for (int i = s; i < e; ++i) {
        size_t cb = (size_t)g_col[i] * 64;
        a0 += __half2float(hs[cb + lane]);
        if (lane < 8) a1 += __half2float(hs[cb + 32 + lane]);
    }
    float v0 = fmaf(a0, d, bl[lane]);
    float v1 = (lane < 8) ? fmaf(a1, d, bl[32 + lane]) : 0.f;

    float m = v0;
    if (lane < 8) m = fmaxf(m, v1);
    #pragma unroll
    for (int off = 16; off > 0; off >>= 1)
        m = fmaxf(m, __shfl_xor_sync(0xffffffffu, m, off));
    float sum = expf(v0 - m) + ((lane < 8) ? expf(v1 - m) : 0.f);
    #pragma unroll
    for (int off = 16; off > 0; off >>= 1)
        sum += __shfl_xor_sync(0xffffffffu, sum, off);
    float lse = logf(sum);
    size_t ob = (size_t)row * D_O;
    out[ob + lane] = v0 - m - lse;
    if (lane < 8) out[ob + 32 + lane] = v1 - m - lse;
}

// ---------------- PDL launch helper ------------------------------------------
template <typename F, typename... Args>
static void launchP(F* k, int grid, int block, size_t smem, Args... args) {
    cudaLaunchConfig_t cfg = {};
    cfg.gridDim = dim3(grid);
    cfg.blockDim = dim3(block);
    cfg.dynamicSmemBytes = smem;
    cfg.stream = 0;
    cudaLaunchAttribute at[1];
    at[0].id = cudaLaunchAttributeProgrammaticStreamSerialization;
    at[0].val.programmaticStreamSerializationAllowed = 1;
    cfg.attrs = at;
    cfg.numAttrs = 1;
    cudaLaunchKernelEx(&cfg, k, args...);
}

// ---------------- launcher ---------------------------------------------------
extern "C" void kernel_launch(void* const* d_in, const int* in_sizes, int n_in,
                              void* d_out, int out_size) {
    const float* x     = (const float*)d_in[0];
    const float* W0    = (const float*)d_in[1];
    const float* Wh    = (const float*)d_in[3];
    const float* gamma = (const float*)d_in[5];
    const float* beta  = (const float*)d_in[6];
    const float* Wl    = (const float*)d_in[7];
    const float* bl    = (const float*)d_in[8];
    const int*   ei    = (const int*)d_in[9];
    const int* rowE = ei;
    const int* colE = ei + NE;
    float* out = (float*)d_out;

    __half *pHA, *pHB, *w0, *wh, *wl;
    float *sumA, *sumsqA;
    cudaGetSymbolAddress((void**)&pHA, g_bufHA);
    cudaGetSymbolAddress((void**)&pHB, g_bufHB);
    cudaGetSymbolAddress((void**)&w0, g_w0);
    cudaGetSymbolAddress((void**)&wh, g_wh);
    cudaGetSymbolAddress((void**)&wl, g_wl);
    cudaGetSymbolAddress((void**)&sumA, g_sumA);
    cudaGetSymbolAddress((void**)&sumsqA, g_sumsqA);

    constexpr int SMEM256 = 2 * (16384 + 256 * 128);  // 98304
    constexpr int SMEM64  = 2 * (16384 + 64 * 128);   // 49152
    cudaFuncSetAttribute(gemm_mma_kernel<128, 256, false, false, true>,
                         cudaFuncAttributeMaxDynamicSharedMemorySize, SMEM256);
    cudaFuncSetAttribute(gemm_mma_kernel<256, 256, true, true, false>,
                         cudaFuncAttributeMaxDynamicSharedMemorySize, SMEM256);
    cudaFuncSetAttribute(gemm_mma_kernel<256, 64, true, true, false>,
                         cudaFuncAttributeMaxDynamicSharedMemorySize, SMEM64);

    const int EB = (NE + 255) / 256;       // 6250
    const int NBLK = (NN + 255) / 256;
    const int MT = (NN + 127) / 128;       // 782
    const int SPB = NN / 32;               // 3125 (32 rows per block)
    const int XB = (NN * 32 + 255) / 256;  // 12500

    // prep chain (normal launches)
    prep_kernel<<<EB, 256>>>(W0, Wh, Wl, rowE);
    scan1_kernel<<<SCAN_BLOCKS, 1024>>>();
    scan2_kernel<<<1, 128>>>();
    scan3_kernel<<<NBLK, 256>>>();
    csr_x_kernel<<<XB, 256>>>(rowE, colE, x, pHA);

    // layer 0 (PDL chain from here)
    launchP(&spmmh_kernel<false, 128>, SPB, 512, (size_t)0,
            (const __half*)pHA, (__half*)pHB, (float*)nullptr, (float*)nullptr);
    launchP(&gemm_mma_kernel<128, 256, false, false, true>, MT, 512, (size_t)SMEM256,
            (const __half*)pHB, (const __half*)w0, (__half*)pHA,
            (const float*)nullptr, (const float*)nullptr,
            (const float*)nullptr, (const float*)nullptr,
            (float*)sumA, (float*)sumsqA);

    // hidden layers 1..3
    for (int l = 0; l < 3; ++l) {
        launchP(&gemm_mma_kernel<256, 256, true, true, false>, MT, 512, (size_t)SMEM256,
                (const __half*)pHA, (const __half*)(wh + (size_t)l * 65536), (__half*)pHB,
                (const float*)(sumA + (size_t)l * 256), (const float*)(sumsqA + (size_t)l * 256),
                (const float*)(gamma + (size_t)l * 256), (const float*)(beta + (size_t)l * 256),
                (float*)nullptr, (float*)nullptr);
        launchP(&spmmh_kernel<true, 256>, SPB, 512, (size_t)0,
                (const __half*)pHB, (__half*)pHA,
                (float*)(sumA + (size_t)(l + 1) * 256),
                (float*)(sumsqA + (size_t)(l + 1) * 256));
    }

    // final layer + softmax
    launchP(&gemm_mma_kernel<256, 64, true, true, false>, MT, 512, (size_t)SMEM64,
            (const __half*)pHA, (const __half*)wl, (__half*)pHB,
            (const float*)(sumA + 3 * 256), (const float*)(sumsqA + 3 * 256),
            (const float*)(gamma + 3 * 256), (const float*)(beta + 3 * 256),
            (float*)nullptr, (float*)nullptr);
    launchP(&spmm40_softmax_kernel, NN / 8, 256, (size_t)0,
            (const __half*)pHB, (const float*)bl, (float*)out);
}

// round 15
// speedup vs baseline: 1.0663x; 1.0663x over previous
#include <cuda_runtime.h>
#include <cuda_fp16.h>
#include <math.h>
#include <stdint.h>

#define NN    100000
#define NE    1600000
#define D_INF 128
#define D_H   256
#define D_O   40
#define SCAN_BLOCKS ((NN + 1023) / 1024)

// ---------------- scratch (device globals; no allocation allowed) ----------
__device__ __align__(256) __half g_bufHA[(size_t)NN * D_H];
__device__ __align__(256) __half g_bufHB[(size_t)NN * D_H];
__device__ int   g_deg[NN];          // zeroed by csr_x_kernel of previous replay (zero-init first run)
__device__ float g_dinv[NN];
__device__ int   g_rowptr[NN + 1];
__device__ int   g_cursor[NN];
__device__ int   g_col[NE];
__device__ int   g_bsum[256];
__device__ float g_sumA[4 * 256];    // per-layer BN stats slots
__device__ float g_sumsqA[4 * 256];
__device__ __align__(256) __half g_w0[256 * 128];
__device__ __align__(256) __half g_wh[3 * 256 * 256];
__device__ __align__(256) __half g_wl[64 * 256];

// ---------------- helpers ----------------------------------------------------
__device__ __forceinline__ uint32_t smem_u32(const void* p) {
    uint32_t a;
    asm("{ .reg .u64 t; cvta.to.shared.u64 t, %1; cvt.u32.u64 %0, t; }" : "=r"(a) : "l"(p));
    return a;
}
#define SW128(o) ((o) ^ (((o) >> 3) & 0x70))

__device__ __forceinline__ void ldm_x4(uint32_t* r, uint32_t addr) {
    asm volatile("ldmatrix.sync.aligned.m8n8.x4.shared.b16 {%0,%1,%2,%3}, [%4];"
                 : "=r"(r[0]), "=r"(r[1]), "=r"(r[2]), "=r"(r[3]) : "r"(addr));
}
__device__ __forceinline__ void mma_f16(float* c, const uint32_t* a, uint32_t b0, uint32_t b1) {
    asm volatile(
        "mma.sync.aligned.m16n8k16.row.col.f32.f16.f16.f32 "
        "{%0,%1,%2,%3}, {%4,%5,%6,%7}, {%8,%9}, {%0,%1,%2,%3};"
        : "+f"(c[0]), "+f"(c[1]), "+f"(c[2]), "+f"(c[3])
        : "r"(a[0]), "r"(a[1]), "r"(a[2]), "r"(a[3]), "r"(b0), "r"(b1));
}
__device__ __forceinline__ void cp16(uint32_t dst, const void* src) {
    asm volatile("cp.async.cg.shared.global [%0], [%1], 16;" :: "r"(dst), "l"(src));
}
#define CP_COMMIT() asm volatile("cp.async.commit_group;" ::: "memory")
#define CP_WAIT0()  asm volatile("cp.async.wait_group 0;" ::: "memory")

// ---------------- prep: weight convert + degree count + stats zero ----------
#define CVT_TOTAL (32768 + 196608 + 16384)
__global__ void prep_kernel(const float* __restrict__ W0,
                            const float* __restrict__ Wh,
                            const float* __restrict__ Wl,
                            const int* __restrict__ rowE) {
    int i = blockIdx.x * 256 + threadIdx.x;
    if (i < NE) atomicAdd(&g_deg[rowE[i]], 1);
    if (i < 1024) { g_sumA[i] = 0.f; g_sumsqA[i] = 0.f; }
    if (i < 32768) {
        int n = i >> 7, k = i & 127;
        g_w0[i] = __float2half_rn(W0[k * 256 + n]);
    } else if (i < 229376) {
        int j = i - 32768;
        int l = j >> 16, r = j & 65535;
        int n = r >> 8, k = r & 255;
        g_wh[j] = __float2half_rn(Wh[l * 65536 + k * 256 + n]);
    } else if (i < CVT_TOTAL) {
        int j = i - 229376;
        int n = j >> 8, k = j & 255;
        g_wl[j] = __float2half_rn((n < D_O) ? Wl[k * D_O + n] : 0.f);
    }
}

// ---------------- scans ------------------------------------------------------
__global__ void scan1_kernel() {
    __shared__ int sm[1024];
    int tid = threadIdx.x;
    int i = blockIdx.x * 1024 + tid;
    int v = (i < NN) ? g_deg[i] : 0;
    int x = v;
    sm[tid] = x;
    __syncthreads();
    #pragma unroll
    for (int off = 1; off < 1024; off <<= 1) {
        int t = (tid >= off) ? sm[tid - off] : 0;
        __syncthreads();
        x += t;
        sm[tid] = x;
        __syncthreads();
    }
    if (i < NN) g_rowptr[i] = x - v;
    if (tid == 1023) g_bsum[blockIdx.x] = x;
}
__global__ void scan2_kernel() {
    __shared__ int sm[128];
    int tid = threadIdx.x;
    int v = (tid < SCAN_BLOCKS) ? g_bsum[tid] : 0;
    int x = v;
    sm[tid] = x;
    __syncthreads();
    #pragma unroll
    for (int off = 1; off < 128; off <<= 1) {
        int t = (tid >= off) ? sm[tid - off] : 0;
        __syncthreads();
        x += t;
        sm[tid] = x;
        __syncthreads();
    }
    if (tid < SCAN_BLOCKS) g_bsum[tid] = x - v;
    if (tid == 127) g_rowptr[NN] = x;
}
__global__ void scan3_kernel() {
    int i = blockIdx.x * blockDim.x + threadIdx.x;
    if (i >= NN) return;
    int rp = g_rowptr[i] + g_bsum[i >> 10];
    g_rowptr[i] = rp;
    g_cursor[i] = rp;
    g_dinv[i] = rsqrtf((float)(g_deg[i] + 1));
}

// ---------------- CSR fill + x->fp16*dinv + deg reset (one launch) ----------
__global__ void csr_x_kernel(const int* __restrict__ rowE, const int* __restrict__ colE,
                             const float* __restrict__ x, __half* __restrict__ xh) {
    int i = blockIdx.x * 256 + threadIdx.x;     // 0 .. NN*32 (3.2M)
    if (i < NE) {
        int p = atomicAdd(&g_cursor[rowE[i]], 1);
        g_col[p] = colE[i];
    }
    if (i < NN) g_deg[i] = 0;                   // reset for next replay
    if (i < NN * 32) {                          // float4 index
        int row = i >> 5;
        float d = g_dinv[row];
        float4 v = reinterpret_cast<const float4*>(x)[i];
        __half2 a = __floats2half2_rn(v.x * d, v.y * d);
        __half2 b = __floats2half2_rn(v.z * d, v.w * d);
        uint2 u;
        u.x = *reinterpret_cast<uint32_t*>(&a);
        u.y = *reinterpret_cast<uint32_t*>(&b);
        reinterpret_cast<uint2*>(xh)[i] = u;
    }
}

// ---------------- pipelined warp-MMA single-product fp16 GEMM (PDL) ---------
template <int KTOT, int NT, bool BN, bool SCALE, bool STATS>
__global__ __launch_bounds__(512)
void gemm_mma_kernel(const __half* __restrict__ A,
                     const __half* __restrict__ W,
                     __half* __restrict__ C,
                     const float* __restrict__ statsS,
                     const float* __restrict__ statsQ,
                     const float* __restrict__ gamma,
                     const float* __restrict__ beta,
                     float* __restrict__ outS,
                     float* __restrict__ outQ) {
    constexpr int OF_B = 16384;               // A: 128 rows x 128B
    constexpr int STG = 16384 + NT * 128;
    constexpr int NPW = NT / 4;
    constexpr int NI = NPW / 8;
    constexpr int KCH = KTOT / 64;

    extern __shared__ __align__(1024) char smem[];
    __shared__ float s_scale[256];
    __shared__ float s_shift[256];
    uint32_t sb = smem_u32(smem);
    int tid = threadIdx.x, lane = tid & 31, wid = tid >> 5;
    int wm = wid >> 2, wn = wid & 3;
    int rowBase = blockIdx.x * 128;

    int cg = (tid & 7) * 8;
    int rr = tid >> 3;
    uint4 av[2];

    auto cpB = [&](int ch, int s) {
        int k0 = ch * 64;
        uint32_t base = sb + s * STG;
        #pragma unroll
        for (int p = 0; p < NT / 64; ++p) {
            int n = rr + p * 64;
            size_t go = (size_t)n * KTOT + k0 + cg;
            uint32_t off = SW128((uint32_t)(n * 128 + cg * 2));
            cp16(base + OF_B + off, W + go);
        }
    };

    // ---- PDL prologue: W is constant (written by prep, long complete) ----
    cpB(0, 0);
    cudaGridDependencySynchronize();

    if (BN) {
        if (tid < 256) {
            float s = statsS[tid];
            float q = statsQ[tid];
            float mu = s * (1.f / NN);
            float var = q * (1.f / NN) - mu * mu;
            float sc = rsqrtf(var + 1e-5f) * gamma[tid];
            s_scale[tid] = sc;
            s_shift[tid] = beta[tid] - mu * sc;
        }
        __syncthreads();
    }

    float acc[2][NI][4];
    #pragma unroll
    for (int mi = 0; mi < 2; ++mi)
        #pragma unroll
        for (int ni = 0; ni < NI; ++ni)
            #pragma unroll
            for (int q = 0; q < 4; ++q) acc[mi][ni][q] = 0.f;

    auto ldgA = [&](int ch) {
        int k0 = ch * 64;
        #pragma unroll
        for (int p = 0; p < 2; ++p) {
            int gr = rowBase + rr + p * 64;
            if (gr < NN)
                av[p] = *reinterpret_cast<const uint4*>(A + (size_t)gr * KTOT + k0 + cg);
            else
                av[p] = make_uint4(0, 0, 0, 0);
        }
    };
    auto stsA = [&](int ch, int s) {
        int k0 = ch * 64;
        char* base = smem + s * STG;
        #pragma unroll
        for (int p = 0; p < 2; ++p) {
            __half2* hp = reinterpret_cast<__half2*>(&av[p]);
            uint4 o;
            __half2* op = reinterpret_cast<__half2*>(&o);
            #pragma unroll
            for (int j = 0; j < 4; ++j) {
                float2 f = __half22float2(hp[j]);
                int c = k0 + cg + j * 2;
                f.x = fmaxf(fmaf(f.x, s_scale[c], s_shift[c]), 0.f);
                f.y = fmaxf(fmaf(f.y, s_scale[c + 1], s_shift[c + 1]), 0.f);
                op[j] = __floats2half2_rn(f.x, f.y);
            }
            uint32_t off = SW128((uint32_t)((rr + p * 64) * 128 + cg * 2));
            *reinterpret_cast<uint4*>(base + off) = o;
        }
    };
    auto cpA = [&](int ch, int s) {
        int k0 = ch * 64;
        uint32_t base = sb + s * STG;
        #pragma unroll
        for (int p = 0; p < 2; ++p) {
            int gr = rowBase + rr + p * 64;
            uint32_t off = SW128((uint32_t)((rr + p * 64) * 128 + cg * 2));
            if (gr < NN)
                cp16(base + off, A + (size_t)gr * KTOT + k0 + cg);
            else
                *reinterpret_cast<uint4*>(smem + s * STG + off) = make_uint4(0, 0, 0, 0);
        }
    };
    auto domma = [&](int s) {
        uint32_t aF = sb + s * STG;
        uint32_t bF = aF + OF_B;
        #pragma unroll
        for (int ks = 0; ks < 4; ++ks) {
            int kk = ks * 16;
            uint32_t af[2][4];
            #pragma unroll
            for (int mi = 0; mi < 2; ++mi) {
                int r = wm * 32 + mi * 16 + (lane & 15);
                int c = kk + (lane >> 4) * 8;
                uint32_t off = SW128((uint32_t)(r * 128 + c * 2));
                ldm_x4(af[mi], aF + off);
            }
            #pragma unroll
            for (int nt = 0; nt < NI / 2; ++nt) {
                int g = lane >> 3;
                int row = wn * NPW + nt * 16 + (g >> 1) * 8 + (lane & 7);
                int c = kk + (g & 1) * 8;
                uint32_t off = SW128((uint32_t)(row * 128 + c * 2));
                uint32_t bh[4];
                ldm_x4(bh, bF + off);
                #pragma unroll
                for (int half = 0; half < 2; ++half) {
                    int ni = nt * 2 + half;
                    #pragma unroll
                    for (int mi = 0; mi < 2; ++mi)
                        mma_f16(acc[mi][ni], af[mi], bh[half * 2], bh[half * 2 + 1]);
                }
            }
        }
    };

    if (BN) ldgA(0); else cpA(0, 0);
    CP_COMMIT();
    if (BN) stsA(0, 0);

    for (int ch = 0; ch < KCH; ++ch) {
        int s = ch & 1;
        CP_WAIT0();
        __syncthreads();
        if (ch + 1 < KCH) {
            if (BN) ldgA(ch + 1); else cpA(ch + 1, s ^ 1);
            cpB(ch + 1, s ^ 1);
            CP_COMMIT();
        }
        domma(s);
        if (BN && ch + 1 < KCH) stsA(ch + 1, s ^ 1);
    }

    // epilogue: fp16 store (x dinv if SCALE)
    #pragma unroll
    for (int mi = 0; mi < 2; ++mi) {
        int r0 = rowBase + wm * 32 + mi * 16 + (lane >> 2);
        int r1 = r0 + 8;
        float d0 = 1.f, d1 = 1.f;
        if (SCALE) {
            d0 = (r0 < NN) ? g_dinv[r0] : 0.f;
            d1 = (r1 < NN) ? g_dinv[r1] : 0.f;
        }
        #pragma unroll
        for (int ni = 0; ni < NI; ++ni) {
            int c0 = wn * NPW + ni * 8 + (lane & 3) * 2;
            if (r0 < NN)
                *reinterpret_cast<__half2*>(C + (size_t)r0 * NT + c0) =
                    __floats2half2_rn(acc[mi][ni][0] * d0, acc[mi][ni][1] * d0);
            if (r1 < NN)
                *reinterpret_cast<__half2*>(C + (size_t)r1 * NT + c0) =
                    __floats2half2_rn(acc[mi][ni][2] * d1, acc[mi][ni][3] * d1);
        }
    }

    // fused BN stats (layer-0 GEMM): fp32 accumulators, padding rows are zero
    if constexpr (STATS) {
        __shared__ float s_sum[256];
        __shared__ float s_sq[256];
        if (tid < 256) { s_sum[tid] = 0.f; s_sq[tid] = 0.f; }
        __syncthreads();
        #pragma unroll
        for (int ni = 0; ni < NI; ++ni) {
            float s0 = 0.f, q0 = 0.f, s1 = 0.f, q1 = 0.f;
            #pragma unroll
            for (int mi = 0; mi < 2; ++mi) {
                float va = acc[mi][ni][0], vb = acc[mi][ni][2];
                s0 += va + vb; q0 += va * va + vb * vb;
                float vc = acc[mi][ni][1], vd = acc[mi][ni][3];
                s1 += vc + vd; q1 += vc * vc + vd * vd;
            }
            #pragma unroll
            for (int off = 4; off <= 16; off <<= 1) {
                s0 += __shfl_xor_sync(0xffffffffu, s0, off);
                q0 += __shfl_xor_sync(0xffffffffu, q0, off);
                s1 += __shfl_xor_sync(0xffffffffu, s1, off);
                q1 += __shfl_xor_sync(0xffffffffu, q1, off);
            }
            if ((lane >> 2) == 0) {
                int c0 = wn * NPW + ni * 8 + (lane & 3) * 2;
                atomicAdd(&s_sum[c0], s0);
                atomicAdd(&s_sq[c0], q0);
                atomicAdd(&s_sum[c0 + 1], s1);
                atomicAdd(&s_sq[c0 + 1], q1);
            }
        }
        __syncthreads();
        if (tid < 256) {
            atomicAdd(&outS[tid], s_sum[tid]);
            atomicAdd(&outQ[tid], s_sq[tid]);
        }
    }
}

// ---------------- SpMM fp16 in -> fp16 out (+fp32 stats to slot), PDL -------
template <bool STATS, int COLS>
__global__ __launch_bounds__(512)
void spmmh_kernel(const __half* __restrict__ in, __half* __restrict__ out,
                  float* __restrict__ outS, float* __restrict__ outQ) {
    constexpr int CPL = COLS / 32;
    int warp = threadIdx.x >> 5, lane = threadIdx.x & 31;
    int row = blockIdx.x * 16 + warp;

    int s = g_rowptr[row], e = g_rowptr[row + 1];
    float d = g_dinv[row];
    cudaGridDependencySynchronize();

    float acc[CPL];
    {
        const __half2* p = reinterpret_cast<const __half2*>(in + (size_t)row * COLS + lane * CPL);
        #pragma unroll
        for (int j = 0; j < CPL / 2; ++j) {
            float2 f = __half22float2(p[j]);
            acc[j * 2] = f.x;
            acc[j * 2 + 1] = f.y;
        }
    }
    for (int i = s; i < e; ++i) {
        int c = g_col[i];
        const __half* p = in + (size_t)c * COLS + lane * CPL;
        if constexpr (CPL == 8) {
            uint4 u = *reinterpret_cast<const uint4*>(p);
            __half2* hp = reinterpret_cast<__half2*>(&u);
            #pragma unroll
            for (int j = 0; j < 4; ++j) {
                float2 f = __half22float2(hp[j]);
                acc[j * 2] += f.x;
                acc[j * 2 + 1] += f.y;
            }
        } else {
            uint2 u = *reinterpret_cast<const uint2*>(p);
            __half2* hp = reinterpret_cast<__half2*>(&u);
            #pragma unroll
            for (int j = 0; j < 2; ++j) {
                float2 f = __half22float2(hp[j]);
                acc[j * 2] += f.x;
                acc[j * 2 + 1] += f.y;
            }
        }
    }
    #pragma unroll
    for (int j = 0; j < CPL; ++j) acc[j] *= d;

    {
        __half2 o[CPL / 2];
        #pragma unroll
        for (int j = 0; j < CPL / 2; ++j)
            o[j] = __floats2half2_rn(acc[j * 2], acc[j * 2 + 1]);
        __half* op = out + (size_t)row * COLS + lane * CPL;
        if constexpr (CPL == 8)
            *reinterpret_cast<uint4*>(op) = *reinterpret_cast<uint4*>(o);
        else
            *reinterpret_cast<uint2*>(op) = *reinterpret_cast<uint2*>(o);
    }

    if constexpr (STATS) {
        __shared__ float ss[16][COLS];
        __shared__ float sq[16][COLS];
        #pragma unroll
        for (int j = 0; j < CPL; ++j) {
            ss[warp][lane * CPL + j] = acc[j];
            sq[warp][lane * CPL + j] = acc[j] * acc[j];
        }
        __syncthreads();
        int t = threadIdx.x;
        if (t < COLS) {
            float sm = 0.f;
            #pragma unroll
            for (int w = 0; w < 16; ++w) sm += ss[w][t];
            atomicAdd(&outS[t], sm);
        } else if (t < 2 * COLS) {
            int c = t - COLS;
            float sm = 0.f;
            #pragma unroll
            for (int w = 0; w < 16; ++w) sm += sq[w][c];
            atomicAdd(&outQ[c], sm);
        }
    }
}

// ---------------- final SpMM (64-stride fp16 in) + log_softmax, PDL ---------
__global__ __launch_bounds__(256)
void spmm40_softmax_kernel(const __half* __restrict__ hs,
                           const float* __restrict__ bl,
                           float* __restrict__ out) {
    int warp = threadIdx.x >> 5, lane = threadIdx.x & 31;
    int row = blockIdx.x * 8 + warp;
    int s = 0, e = 0;
    float d = 0.f;
    if (row < NN) {
        s = g_rowptr[row];
        e = g_rowptr[row + 1];
        d = g_dinv[row];
    }
    cudaGridDependencySynchronize();
    if (row >= NN) return;

    size_t rbase = (size_t)row * 64;
    float a0 = __half2float(hs[rbase + lane]);
    float a1 = (lane < 8) ? __half2float(hs[rbase + 32 + lane]) : 0.f;
    for (int i = s; i < e; ++i) {
        size_t cb = (size_t)g_col[i] * 64;
        a0 += __half2float(hs[cb + lane]);
        if (lane < 8) a1 += __half2float(hs[cb + 32 + lane]);
    }
    float v0 = fmaf(a0, d, bl[lane]);
    float v1 = (lane < 8) ? fmaf(a1, d, bl[32 + lane]) : 0.f;

    float m = v0;
    if (lane < 8) m = fmaxf(m, v1);
    #pragma unroll
    for (int off = 16; off > 0; off >>= 1)
        m = fmaxf(m, __shfl_xor_sync(0xffffffffu, m, off));
    float sum = __expf(v0 - m) + ((lane < 8) ? __expf(v1 - m) : 0.f);
    #pragma unroll
    for (int off = 16; off > 0; off >>= 1)
        sum += __shfl_xor_sync(0xffffffffu, sum, off);
    float lse = __logf(sum);
    size_t ob = (size_t)row * D_O;
    out[ob + lane] = v0 - m - lse;
    if (lane < 8) out[ob + 32 + lane] = v1 - m - lse;
}

// ---------------- PDL launch helper ------------------------------------------
template <typename F, typename... Args>
static void launchP(F* k, int grid, int block, size_t smem, Args... args) {
    cudaLaunchConfig_t cfg = {};
    cfg.gridDim = dim3(grid);
    cfg.blockDim = dim3(block);
    cfg.dynamicSmemBytes = smem;
    cfg.stream = 0;
    cudaLaunchAttribute at[1];
    at[0].id = cudaLaunchAttributeProgrammaticStreamSerialization;
    at[0].val.programmaticStreamSerializationAllowed = 1;
    cfg.attrs = at;
    cfg.numAttrs = 1;
    cudaLaunchKernelEx(&cfg, k, args...);
}

// ---------------- launcher ---------------------------------------------------
extern "C" void kernel_launch(void* const* d_in, const int* in_sizes, int n_in,
                              void* d_out, int out_size) {
    const float* x     = (const float*)d_in[0];
    const float* W0    = (const float*)d_in[1];
    const float* Wh    = (const float*)d_in[3];
    const float* gamma = (const float*)d_in[5];
    const float* beta  = (const float*)d_in[6];
    const float* Wl    = (const float*)d_in[7];
    const float* bl    = (const float*)d_in[8];
    const int*   ei    = (const int*)d_in[9];
    const int* rowE = ei;
    const int* colE = ei + NE;
    float* out = (float*)d_out;

    __half *pHA, *pHB, *w0, *wh, *wl;
    float *sumA, *sumsqA;
    cudaGetSymbolAddress((void**)&pHA, g_bufHA);
    cudaGetSymbolAddress((void**)&pHB, g_bufHB);
    cudaGetSymbolAddress((void**)&w0, g_w0);
    cudaGetSymbolAddress((void**)&wh, g_wh);
    cudaGetSymbolAddress((void**)&wl, g_wl);
    cudaGetSymbolAddress((void**)&sumA, g_sumA);
    cudaGetSymbolAddress((void**)&sumsqA, g_sumsqA);

    constexpr int SMEM256 = 2 * (16384 + 256 * 128);  // 98304
    constexpr int SMEM64  = 2 * (16384 + 64 * 128);   // 49152
    cudaFuncSetAttribute(gemm_mma_kernel<128, 256, false, false, true>,
                         cudaFuncAttributeMaxDynamicSharedMemorySize, SMEM256);
    cudaFuncSetAttribute(gemm_mma_kernel<256, 256, true, true, false>,
                         cudaFuncAttributeMaxDynamicSharedMemorySize, SMEM256);
    cudaFuncSetAttribute(gemm_mma_kernel<256, 64, true, true, false>,
                         cudaFuncAttributeMaxDynamicSharedMemorySize, SMEM64);

    const int EB = (NE + 255) / 256;       // 6250
    const int NBLK = (NN + 255) / 256;
    const int MT = (NN + 127) / 128;       // 782
    const int SPB = NN / 16;               // 6250
    const int XB = (NN * 32 + 255) / 256;  // 12500

    // prep chain (normal launches)
    prep_kernel<<<EB, 256>>>(W0, Wh, Wl, rowE);
    scan1_kernel<<<SCAN_BLOCKS, 1024>>>();
    scan2_kernel<<<1, 128>>>();
    scan3_kernel<<<NBLK, 256>>>();
    csr_x_kernel<<<XB, 256>>>(rowE, colE, x, pHA);

    // layer 0 (PDL chain from here)
    launchP(&spmmh_kernel<false, 128>, SPB, 512, (size_t)0,
            (const __half*)pHA, (__half*)pHB, (float*)nullptr, (float*)nullptr);
    launchP(&gemm_mma_kernel<128, 256, false, false, true>, MT, 512, (size_t)SMEM256,
            (const __half*)pHB, (const __half*)w0, (__half*)pHA,
            (const float*)nullptr, (const float*)nullptr,
            (const float*)nullptr, (const float*)nullptr,
            (float*)sumA, (float*)sumsqA);

    // hidden layers 1..3
    for (int l = 0; l < 3; ++l) {
        launchP(&gemm_mma_kernel<256, 256, true, true, false>, MT, 512, (size_t)SMEM256,
                (const __half*)pHA, (const __half*)(wh + (size_t)l * 65536), (__half*)pHB,
                (const float*)(sumA + (size_t)l * 256), (const float*)(sumsqA + (size_t)l * 256),
                (const float*)(gamma + (size_t)l * 256), (const float*)(beta + (size_t)l * 256),
                (float*)nullptr, (float*)nullptr);
        launchP(&spmmh_kernel<true, 256>, SPB, 512, (size_t)0,
                (const __half*)pHB, (__half*)pHA,
                (float*)(sumA + (size_t)(l + 1) * 256),
                (float*)(sumsqA + (size_t)(l + 1) * 256));
    }

    // final layer + softmax
    launchP(&gemm_mma_kernel<256, 64, true, true, false>, MT, 512, (size_t)SMEM64,
            (const __half*)pHA, (const __half*)wl, (__half*)pHB,
            (const float*)(sumA + 3 * 256), (const float*)(sumsqA + 3 * 256),
            (const float*)(gamma + 3 * 256), (const float*)(beta + 3 * 256),
            (float*)nullptr, (float*)nullptr);
    launchP(&spmm40_softmax_kernel, NN / 8, 256, (size_t)0,
            (const __half*)pHB, (const float*)bl, (float*)out);
}

// round 16
// speedup vs baseline: 1.0681x; 1.0017x over previous
#include <cuda_runtime.h>
#include <cuda_fp16.h>
#include <math.h>
#include <stdint.h>

#define NN    100000
#define NE    1600000
#define D_INF 128
#define D_H   256
#define D_O   40
#define SCAN_BLOCKS ((NN + 1023) / 1024)

// ---------------- scratch (device globals; no allocation allowed) ----------
__device__ __align__(256) __half g_bufHA[(size_t)NN * D_H];
__device__ __align__(256) __half g_bufHB[(size_t)NN * D_H];
__device__ int   g_deg[NN];          // zeroed by csr_x_kernel of previous replay (zero-init first run)
__device__ float g_dinv[NN];
__device__ int   g_rowptr[NN + 1];
__device__ int   g_cursor[NN];
__device__ int   g_col[NE];
__device__ int   g_scanFlag[SCAN_BLOCKS];   // zeroed by prep_kernel each call
__device__ int   g_scanAgg[SCAN_BLOCKS];
__device__ float g_sumA[4 * 256];    // per-layer BN stats slots
__device__ float g_sumsqA[4 * 256];
__device__ __align__(256) __half g_w0[256 * 128];
__device__ __align__(256) __half g_wh[3 * 256 * 256];
__device__ __align__(256) __half g_wl[64 * 256];

// ---------------- helpers ----------------------------------------------------
__device__ __forceinline__ uint32_t smem_u32(const void* p) {
    uint32_t a;
    asm("{ .reg .u64 t; cvta.to.shared.u64 t, %1; cvt.u32.u64 %0, t; }" : "=r"(a) : "l"(p));
    return a;
}
#define SW128(o) ((o) ^ (((o) >> 3) & 0x70))

__device__ __forceinline__ void ldm_x4(uint32_t* r, uint32_t addr) {
    asm volatile("ldmatrix.sync.aligned.m8n8.x4.shared.b16 {%0,%1,%2,%3}, [%4];"
                 : "=r"(r[0]), "=r"(r[1]), "=r"(r[2]), "=r"(r[3]) : "r"(addr));
}
__device__ __forceinline__ void mma_f16(float* c, const uint32_t* a, uint32_t b0, uint32_t b1) {
    asm volatile(
        "mma.sync.aligned.m16n8k16.row.col.f32.f16.f16.f32 "
        "{%0,%1,%2,%3}, {%4,%5,%6,%7}, {%8,%9}, {%0,%1,%2,%3};"
        : "+f"(c[0]), "+f"(c[1]), "+f"(c[2]), "+f"(c[3])
        : "r"(a[0]), "r"(a[1]), "r"(a[2]), "r"(a[3]), "r"(b0), "r"(b1));
}
__device__ __forceinline__ void cp16(uint32_t dst, const void* src) {
    asm volatile("cp.async.cg.shared.global [%0], [%1], 16;" :: "r"(dst), "l"(src));
}
#define CP_COMMIT() asm volatile("cp.async.commit_group;" ::: "memory")
#define CP_WAIT0()  asm volatile("cp.async.wait_group 0;" ::: "memory")

// ---------------- prep: weight convert + degree count + stats/flag zero -----
#define CVT_TOTAL (32768 + 196608 + 16384)
__global__ void prep_kernel(const float* __restrict__ W0,
                            const float* __restrict__ Wh,
                            const float* __restrict__ Wl,
                            const int* __restrict__ rowE) {
    // full serialization with the previous kernel (cross-replay CSR safety)
    cudaGridDependencySynchronize();
    int i = blockIdx.x * 256 + threadIdx.x;
    if (i < NE) atomicAdd(&g_deg[rowE[i]], 1);
    if (i < 1024) { g_sumA[i] = 0.f; g_sumsqA[i] = 0.f; }
    if (i < SCAN_BLOCKS) g_scanFlag[i] = 0;
    if (i < 32768) {
        int n = i >> 7, k = i & 127;
        g_w0[i] = __float2half_rn(W0[k * 256 + n]);
    } else if (i < 229376) {
        int j = i - 32768;
        int l = j >> 16, r = j & 65535;
        int n = r >> 8, k = r & 255;
        g_wh[j] = __float2half_rn(Wh[l * 65536 + k * 256 + n]);
    } else if (i < CVT_TOTAL) {
        int j = i - 229376;
        int n = j >> 8, k = j & 255;
        g_wl[j] = __float2half_rn((n < D_O) ? Wl[k * D_O + n] : 0.f);
    }
}

// ---------------- single-kernel scan (all blocks co-resident) ---------------
// 98 blocks x 1024 threads: local inclusive scan, publish aggregate, then
// each block sums all predecessor aggregates (parallel spin, block reduce).
__global__ __launch_bounds__(1024)
void scan_kernel() {
    __shared__ int sm[1024];
    __shared__ int wsum[32];
    __shared__ int s_prev;
    int tid = threadIdx.x, b = blockIdx.x;
    cudaGridDependencySynchronize();        // g_deg from prep
    int i = b * 1024 + tid;
    int v = (i < NN) ? g_deg[i] : 0;
    int x = v;
    sm[tid] = x;
    __syncthreads();
    #pragma unroll
    for (int off = 1; off < 1024; off <<= 1) {
        int t = (tid >= off) ? sm[tid - off] : 0;
        __syncthreads();
        x += t;
        sm[tid] = x;
        __syncthreads();
    }
    // publish block aggregate
    if (tid == 1023) {
        g_scanAgg[b] = x;
        __threadfence();
        atomicExch(&g_scanFlag[b], 1);
    }
    // wait for all predecessors in parallel, then block-reduce their aggregates
    int myv = 0;
    if (tid < b) {
        while (atomicAdd(&g_scanFlag[tid], 0) == 0) {}
        myv = __ldcg(&g_scanAgg[tid]);
    }
    #pragma unroll
    for (int off = 16; off > 0; off >>= 1)
        myv += __shfl_xor_sync(0xffffffffu, myv, off);
    if ((tid & 31) == 0) wsum[tid >> 5] = myv;
    __syncthreads();
    if (tid < 32) {
        int sv = wsum[tid];
        #pragma unroll
        for (int off = 16; off > 0; off >>= 1)
            sv += __shfl_xor_sync(0xffffffffu, sv, off);
        if (tid == 0) s_prev = sv;
    }
    __syncthreads();
    int prev = s_prev;
    if (i < NN) {
        int rp = prev + x - v;              // global exclusive prefix
        g_rowptr[i] = rp;
        g_cursor[i] = rp;
        g_dinv[i] = rsqrtf((float)(v + 1));
    }
    if (b == SCAN_BLOCKS - 1 && tid == 1023) g_rowptr[NN] = prev + x;
}

// ---------------- CSR fill + x->fp16*dinv + deg reset (one launch) ----------
__global__ void csr_x_kernel(const int* __restrict__ rowE, const int* __restrict__ colE,
                             const float* __restrict__ x, __half* __restrict__ xh) {
    cudaGridDependencySynchronize();        // cursor/dinv from scan
    int i = blockIdx.x * 256 + threadIdx.x;     // 0 .. NN*32 (3.2M)
    if (i < NE) {
        int p = atomicAdd(&g_cursor[rowE[i]], 1);
        g_col[p] = colE[i];
    }
    if (i < NN) g_deg[i] = 0;                   // reset for next replay
    if (i < NN * 32) {                          // float4 index
        int row = i >> 5;
        float d = g_dinv[row];
        float4 v = reinterpret_cast<const float4*>(x)[i];
        __half2 a = __floats2half2_rn(v.x * d, v.y * d);
        __half2 b = __floats2half2_rn(v.z * d, v.w * d);
        uint2 u;
        u.x = *reinterpret_cast<uint32_t*>(&a);
        u.y = *reinterpret_cast<uint32_t*>(&b);
        reinterpret_cast<uint2*>(xh)[i] = u;
    }
}

// ---------------- pipelined warp-MMA single-product fp16 GEMM (PDL) ---------
template <int KTOT, int NT, bool BN, bool SCALE, bool STATS>
__global__ __launch_bounds__(512)
void gemm_mma_kernel(const __half* __restrict__ A,
                     const __half* __restrict__ W,
                     __half* __restrict__ C,
                     const float* __restrict__ statsS,
                     const float* __restrict__ statsQ,
                     const float* __restrict__ gamma,
                     const float* __restrict__ beta,
                     float* __restrict__ outS,
                     float* __restrict__ outQ) {
    constexpr int OF_B = 16384;               // A: 128 rows x 128B
    constexpr int STG = 16384 + NT * 128;
    constexpr int NPW = NT / 4;
    constexpr int NI = NPW / 8;
    constexpr int KCH = KTOT / 64;

    extern __shared__ __align__(1024) char smem[];
    __shared__ float s_scale[256];
    __shared__ float s_shift[256];
    uint32_t sb = smem_u32(smem);
    int tid = threadIdx.x, lane = tid & 31, wid = tid >> 5;
    int wm = wid >> 2, wn = wid & 3;
    int rowBase = blockIdx.x * 128;

    int cg = (tid & 7) * 8;
    int rr = tid >> 3;
    uint4 av[2];

    auto cpB = [&](int ch, int s) {
        int k0 = ch * 64;
        uint32_t base = sb + s * STG;
        #pragma unroll
        for (int p = 0; p < NT / 64; ++p) {
            int n = rr + p * 64;
            size_t go = (size_t)n * KTOT + k0 + cg;
            uint32_t off = SW128((uint32_t)(n * 128 + cg * 2));
            cp16(base + OF_B + off, W + go);
        }
    };

    // ---- PDL prologue: W is constant (written by prep, long complete) ----
    cpB(0, 0);
    cudaGridDependencySynchronize();

    if (BN) {
        if (tid < 256) {
            float s = statsS[tid];
            float q = statsQ[tid];
            float mu = s * (1.f / NN);
            float var = q * (1.f / NN) - mu * mu;
            float sc = rsqrtf(var + 1e-5f) * gamma[tid];
            s_scale[tid] = sc;
            s_shift[tid] = beta[tid] - mu * sc;
        }
        __syncthreads();
    }

    float acc[2][NI][4];
    #pragma unroll
    for (int mi = 0; mi < 2; ++mi)
        #pragma unroll
        for (int ni = 0; ni < NI; ++ni)
            #pragma unroll
            for (int q = 0; q < 4; ++q) acc[mi][ni][q] = 0.f;

    auto ldgA = [&](int ch) {
        int k0 = ch * 64;
        #pragma unroll
        for (int p = 0; p < 2; ++p) {
            int gr = rowBase + rr + p * 64;
            if (gr < NN)
                av[p] = *reinterpret_cast<const uint4*>(A + (size_t)gr * KTOT + k0 + cg);
            else
                av[p] = make_uint4(0, 0, 0, 0);
        }
    };
    auto stsA = [&](int ch, int s) {
        int k0 = ch * 64;
        char* base = smem + s * STG;
        #pragma unroll
        for (int p = 0; p < 2; ++p) {
            __half2* hp = reinterpret_cast<__half2*>(&av[p]);
            uint4 o;
            __half2* op = reinterpret_cast<__half2*>(&o);
            #pragma unroll
            for (int j = 0; j < 4; ++j) {
                float2 f = __half22float2(hp[j]);
                int c = k0 + cg + j * 2;
                f.x = fmaxf(fmaf(f.x, s_scale[c], s_shift[c]), 0.f);
                f.y = fmaxf(fmaf(f.y, s_scale[c + 1], s_shift[c + 1]), 0.f);
                op[j] = __floats2half2_rn(f.x, f.y);
            }
            uint32_t off = SW128((uint32_t)((rr + p * 64) * 128 + cg * 2));
            *reinterpret_cast<uint4*>(base + off) = o;
        }
    };
    auto cpA = [&](int ch, int s) {
        int k0 = ch * 64;
        uint32_t base = sb + s * STG;
        #pragma unroll
        for (int p = 0; p < 2; ++p) {
            int gr = rowBase + rr + p * 64;
            uint32_t off = SW128((uint32_t)((rr + p * 64) * 128 + cg * 2));
            if (gr < NN)
                cp16(base + off, A + (size_t)gr * KTOT + k0 + cg);
            else
                *reinterpret_cast<uint4*>(smem + s * STG + off) = make_uint4(0, 0, 0, 0);
        }
    };
    auto domma = [&](int s) {
        uint32_t aF = sb + s * STG;
        uint32_t bF = aF + OF_B;
        #pragma unroll
        for (int ks = 0; ks < 4; ++ks) {
            int kk = ks * 16;
            uint32_t af[2][4];
            #pragma unroll
            for (int mi = 0; mi < 2; ++mi) {
                int r = wm * 32 + mi * 16 + (lane & 15);
                int c = kk + (lane >> 4) * 8;
                uint32_t off = SW128((uint32_t)(r * 128 + c * 2));
                ldm_x4(af[mi], aF + off);
            }
            #pragma unroll
            for (int nt = 0; nt < NI / 2; ++nt) {
                int g = lane >> 3;
                int row = wn * NPW + nt * 16 + (g >> 1) * 8 + (lane & 7);
                int c = kk + (g & 1) * 8;
                uint32_t off = SW128((uint32_t)(row * 128 + c * 2));
                uint32_t bh[4];
                ldm_x4(bh, bF + off);
                #pragma unroll
                for (int half = 0; half < 2; ++half) {
                    int ni = nt * 2 + half;
                    #pragma unroll
                    for (int mi = 0; mi < 2; ++mi)
                        mma_f16(acc[mi][ni], af[mi], bh[half * 2], bh[half * 2 + 1]);
                }
            }
        }
    };

    if (BN) ldgA(0); else cpA(0, 0);
    CP_COMMIT();
    if (BN) stsA(0, 0);

    for (int ch = 0; ch < KCH; ++ch) {
        int s = ch & 1;
        CP_WAIT0();
        __syncthreads();
        if (ch + 1 < KCH) {
            if (BN) ldgA(ch + 1); else cpA(ch + 1, s ^ 1);
            cpB(ch + 1, s ^ 1);
            CP_COMMIT();
        }
        domma(s);
        if (BN && ch + 1 < KCH) stsA(ch + 1, s ^ 1);
    }

    // epilogue: fp16 store (x dinv if SCALE)
    #pragma unroll
    for (int mi = 0; mi < 2; ++mi) {
        int r0 = rowBase + wm * 32 + mi * 16 + (lane >> 2);
        int r1 = r0 + 8;
        float d0 = 1.f, d1 = 1.f;
        if (SCALE) {
            d0 = (r0 < NN) ? g_dinv[r0] : 0.f;
            d1 = (r1 < NN) ? g_dinv[r1] : 0.f;
        }
        #pragma unroll
        for (int ni = 0; ni < NI; ++ni) {
            int c0 = wn * NPW + ni * 8 + (lane & 3) * 2;
            if (r0 < NN)
                *reinterpret_cast<__half2*>(C + (size_t)r0 * NT + c0) =
                    __floats2half2_rn(acc[mi][ni][0] * d0, acc[mi][ni][1] * d0);
            if (r1 < NN)
                *reinterpret_cast<__half2*>(C + (size_t)r1 * NT + c0) =
                    __floats2half2_rn(acc[mi][ni][2] * d1, acc[mi][ni][3] * d1);
        }
    }

    // fused BN stats (layer-0 GEMM): fp32 accumulators, padding rows are zero
    if constexpr (STATS) {
        __shared__ float s_sum[256];
        __shared__ float s_sq[256];
        if (tid < 256) { s_sum[tid] = 0.f; s_sq[tid] = 0.f; }
        __syncthreads();
        #pragma unroll
        for (int ni = 0; ni < NI; ++ni) {
            float s0 = 0.f, q0 = 0.f, s1 = 0.f, q1 = 0.f;
            #pragma unroll
            for (int mi = 0; mi < 2; ++mi) {
                float va = acc[mi][ni][0], vb = acc[mi][ni][2];
                s0 += va + vb; q0 += va * va + vb * vb;
                float vc = acc[mi][ni][1], vd = acc[mi][ni][3];
                s1 += vc + vd; q1 += vc * vc + vd * vd;
            }
            #pragma unroll
            for (int off = 4; off <= 16; off <<= 1) {
                s0 += __shfl_xor_sync(0xffffffffu, s0, off);
                q0 += __shfl_xor_sync(0xffffffffu, q0, off);
                s1 += __shfl_xor_sync(0xffffffffu, s1, off);
                q1 += __shfl_xor_sync(0xffffffffu, q1, off);
            }
            if ((lane >> 2) == 0) {
                int c0 = wn * NPW + ni * 8 + (lane & 3) * 2;
                atomicAdd(&s_sum[c0], s0);
                atomicAdd(&s_sq[c0], q0);
                atomicAdd(&s_sum[c0 + 1], s1);
                atomicAdd(&s_sq[c0 + 1], q1);
            }
        }
        __syncthreads();
        if (tid < 256) {
            atomicAdd(&outS[tid], s_sum[tid]);
            atomicAdd(&outQ[tid], s_sq[tid]);
        }
    }
}

// ---------------- SpMM fp16 in -> fp16 out (+fp32 stats to slot), PDL -------
template <bool STATS, int COLS>
__global__ __launch_bounds__(512)
void spmmh_kernel(const __half* __restrict__ in, __half* __restrict__ out,
                  float* __restrict__ outS, float* __restrict__ outQ) {
    constexpr int CPL = COLS / 32;
    int warp = threadIdx.x >> 5, lane = threadIdx.x & 31;
    int row = blockIdx.x * 16 + warp;

    int s = g_rowptr[row], e = g_rowptr[row + 1];
    float d = g_dinv[row];
    cudaGridDependencySynchronize();

    float acc[CPL];
    {
        const __half2* p = reinterpret_cast<const __half2*>(in + (size_t)row * COLS + lane * CPL);
        #pragma unroll
        for (int j = 0; j < CPL / 2; ++j) {
            float2 f = __half22float2(p[j]);
            acc[j * 2] = f.x;
            acc[j * 2 + 1] = f.y;
        }
    }
    for (int i = s; i < e; ++i) {
        int c = g_col[i];
        const __half* p = in + (size_t)c * COLS + lane * CPL;
        if constexpr (CPL == 8) {
            uint4 u = *reinterpret_cast<const uint4*>(p);
            __half2* hp = reinterpret_cast<__half2*>(&u);
            #pragma unroll
            for (int j = 0; j < 4; ++j) {
                float2 f = __half22float2(hp[j]);
                acc[j * 2] += f.x;
                acc[j * 2 + 1] += f.y;
            }
        } else {
            uint2 u = *reinterpret_cast<const uint2*>(p);
            __half2* hp = reinterpret_cast<__half2*>(&u);
            #pragma unroll
            for (int j = 0; j < 2; ++j) {
                float2 f = __half22float2(hp[j]);
                acc[j * 2] += f.x;
                acc[j * 2 + 1] += f.y;
            }
        }
    }
    #pragma unroll
    for (int j = 0; j < CPL; ++j) acc[j] *= d;

    {
        __half2 o[CPL / 2];
        #pragma unroll
        for (int j = 0; j < CPL / 2; ++j)
            o[j] = __floats2half2_rn(acc[j * 2], acc[j * 2 + 1]);
        __half* op = out + (size_t)row * COLS + lane * CPL;
        if constexpr (CPL == 8)
            *reinterpret_cast<uint4*>(op) = *reinterpret_cast<uint4*>(o);
        else
            *reinterpret_cast<uint2*>(op) = *reinterpret_cast<uint2*>(o);
    }

    if constexpr (STATS) {
        __shared__ float ss[16][COLS];
        __shared__ float sq[16][COLS];
        #pragma unroll
        for (int j = 0; j < CPL; ++j) {
            ss[warp][lane * CPL + j] = acc[j];
            sq[warp][lane * CPL + j] = acc[j] * acc[j];
        }
        __syncthreads();
        int t = threadIdx.x;
        if (t < COLS) {
            float sm = 0.f;
            #pragma unroll
            for (int w = 0; w < 16; ++w) sm += ss[w][t];
            atomicAdd(&outS[t], sm);
        } else if (t < 2 * COLS) {
            int c = t - COLS;
            float sm = 0.f;
            #pragma unroll
            for (int w = 0; w < 16; ++w) sm += sq[w][c];
            atomicAdd(&outQ[c], sm);
        }
    }
}

// ---------------- final SpMM (64-stride fp16 in) + log_softmax, PDL ---------
__global__ __launch_bounds__(256)
void spmm40_softmax_kernel(const __half* __restrict__ hs,
                           const float* __restrict__ bl,
                           float* __restrict__ out) {
    int warp = threadIdx.x >> 5, lane = threadIdx.x & 31;
    int row = blockIdx.x * 8 + warp;
    int s = 0, e = 0;
    float d = 0.f;
    if (row < NN) {
        s = g_rowptr[row];
        e = g_rowptr[row + 1];
        d = g_dinv[row];
    }
    cudaGridDependencySynchronize();
    if (row >= NN) return;

    size_t rbase = (size_t)row * 64;
    float a0 = __half2float(hs[rbase + lane]);
    float a1 = (lane < 8) ? __half2float(hs[rbase + 32 + lane]) : 0.f;
    for (int i = s; i < e; ++i) {
        size_t cb = (size_t)g_col[i] * 64;
        a0 += __half2float(hs[cb + lane]);
        if (lane < 8) a1 += __half2float(hs[cb + 32 + lane]);
    }
    float v0 = fmaf(a0, d, bl[lane]);
    float v1 = (lane < 8) ? fmaf(a1, d, bl[32 + lane]) : 0.f;

    float m = v0;
    if (lane < 8) m = fmaxf(m, v1);
    #pragma unroll
    for (int off = 16; off > 0; off >>= 1)
        m = fmaxf(m, __shfl_xor_sync(0xffffffffu, m, off));
    float sum = __expf(v0 - m) + ((lane < 8) ? __expf(v1 - m) : 0.f);
    #pragma unroll
    for (int off = 16; off > 0; off >>= 1)
        sum += __shfl_xor_sync(0xffffffffu, sum, off);
    float lse = __logf(sum);
    size_t ob = (size_t)row * D_O;
    out[ob + lane] = v0 - m - lse;
    if (lane < 8) out[ob + 32 + lane] = v1 - m - lse;
}

// ---------------- PDL launch helper ------------------------------------------
template <typename F, typename... Args>
static void launchP(F* k, int grid, int block, size_t smem, Args... args) {
    cudaLaunchConfig_t cfg = {};
    cfg.gridDim = dim3(grid);
    cfg.blockDim = dim3(block);
    cfg.dynamicSmemBytes = smem;
    cfg.stream = 0;
    cudaLaunchAttribute at[1];
    at[0].id = cudaLaunchAttributeProgrammaticStreamSerialization;
    at[0].val.programmaticStreamSerializationAllowed = 1;
    cfg.attrs = at;
    cfg.numAttrs = 1;
    cudaLaunchKernelEx(&cfg, k, args...);
}

// ---------------- launcher ---------------------------------------------------
extern "C" void kernel_launch(void* const* d_in, const int* in_sizes, int n_in,
                              void* d_out, int out_size) {
    const float* x     = (const float*)d_in[0];
    const float* W0    = (const float*)d_in[1];
    const float* Wh    = (const float*)d_in[3];
    const float* gamma = (const float*)d_in[5];
    const float* beta  = (const float*)d_in[6];
    const float* Wl    = (const float*)d_in[7];
    const float* bl    = (const float*)d_in[8];
    const int*   ei    = (const int*)d_in[9];
    const int* rowE = ei;
    const int* colE = ei + NE;
    float* out = (float*)d_out;

    __half *pHA, *pHB, *w0, *wh, *wl;
    float *sumA, *sumsqA;
    cudaGetSymbolAddress((void**)&pHA, g_bufHA);
    cudaGetSymbolAddress((void**)&pHB, g_bufHB);
    cudaGetSymbolAddress((void**)&w0, g_w0);
    cudaGetSymbolAddress((void**)&wh, g_wh);
    cudaGetSymbolAddress((void**)&wl, g_wl);
    cudaGetSymbolAddress((void**)&sumA, g_sumA);
    cudaGetSymbolAddress((void**)&sumsqA, g_sumsqA);

    constexpr int SMEM256 = 2 * (16384 + 256 * 128);  // 98304
    constexpr int SMEM64  = 2 * (16384 + 64 * 128);   // 49152
    cudaFuncSetAttribute(gemm_mma_kernel<128, 256, false, false, true>,
                         cudaFuncAttributeMaxDynamicSharedMemorySize, SMEM256);
    cudaFuncSetAttribute(gemm_mma_kernel<256, 256, true, true, false>,
                         cudaFuncAttributeMaxDynamicSharedMemorySize, SMEM256);
    cudaFuncSetAttribute(gemm_mma_kernel<256, 64, true, true, false>,
                         cudaFuncAttributeMaxDynamicSharedMemorySize, SMEM64);

    const int EB = (NE + 255) / 256;       // 6250
    const int MT = (NN + 127) / 128;       // 782
    const int SPB = NN / 16;               // 6250
    const int XB = (NN * 32 + 255) / 256;  // 12500

    // prep chain (PDL; each syncs at top before touching dependent data)
    launchP(&prep_kernel, EB, 256, (size_t)0, W0, Wh, Wl, rowE);
    launchP(&scan_kernel, SCAN_BLOCKS, 1024, (size_t)0);
    launchP(&csr_x_kernel, XB, 256, (size_t)0, rowE, colE, x, (__half*)pHA);

    // layer 0
    launchP(&spmmh_kernel<false, 128>, SPB, 512, (size_t)0,
            (const __half*)pHA, (__half*)pHB, (float*)nullptr, (float*)nullptr);
    launchP(&gemm_mma_kernel<128, 256, false, false, true>, MT, 512, (size_t)SMEM256,
            (const __half*)pHB, (const __half*)w0, (__half*)pHA,
            (const float*)nullptr, (const float*)nullptr,
            (const float*)nullptr, (const float*)nullptr,
            (float*)sumA, (float*)sumsqA);

    // hidden layers 1..3
    for (int l = 0; l < 3; ++l) {
        launchP(&gemm_mma_kernel<256, 256, true, true, false>, MT, 512, (size_t)SMEM256,
                (const __half*)pHA, (const __half*)(wh + (size_t)l * 65536), (__half*)pHB,
                (const float*)(sumA + (size_t)l * 256), (const float*)(sumsqA + (size_t)l * 256),
                (const float*)(gamma + (size_t)l * 256), (const float*)(beta + (size_t)l * 256),
                (float*)nullptr, (float*)nullptr);
        launchP(&spmmh_kernel<true, 256>, SPB, 512, (size_t)0,
                (const __half*)pHB, (__half*)pHA,
                (float*)(sumA + (size_t)(l + 1) * 256),
                (float*)(sumsqA + (size_t)(l + 1) * 256));
    }

    // final layer + softmax
    launchP(&gemm_mma_kernel<256, 64, true, true, false>, MT, 512, (size_t)SMEM64,
            (const __half*)pHA, (const __half*)wl, (__half*)pHB,
            (const float*)(sumA + 3 * 256), (const float*)(sumsqA + 3 * 256),
            (const float*)(gamma + 3 * 256), (const float*)(beta + 3 * 256),
            (float*)nullptr, (float*)nullptr);
    launchP(&spmm40_softmax_kernel, NN / 8, 256, (size_t)0,
            (const __half*)pHB, (const float*)bl, (float*)out);
}

// round 17
// speedup vs baseline: 1.1082x; 1.0375x over previous
#include <cuda_runtime.h>
#include <cuda_fp16.h>
#include <math.h>
#include <stdint.h>

#define NN    100000
#define NE    1600000
#define D_INF 128
#define D_H   256
#define D_O   40
#define SCAN_BLOCKS ((NN + 1023) / 1024)

// ---------------- scratch (device globals; no allocation allowed) ----------
__device__ __align__(256) __half g_bufHA[(size_t)NN * D_H];
__device__ __align__(256) __half g_bufHB[(size_t)NN * D_H];
__device__ int   g_deg[NN];          // zeroed by csr_x_kernel of previous replay (zero-init first run)
__device__ float g_dinv[NN];
__device__ int   g_rowptr[NN + 1];
__device__ int   g_cursor[NN];
__device__ int   g_col[NE];
__device__ int   g_scanFlag[SCAN_BLOCKS];   // zeroed by prep_kernel each call
__device__ int   g_scanAgg[SCAN_BLOCKS];
__device__ float g_sumA[4 * 256];    // per-layer BN stats slots
__device__ float g_sumsqA[4 * 256];
__device__ __align__(256) __half g_w0[256 * 128];
__device__ __align__(256) __half g_wh[3 * 256 * 256];
__device__ __align__(256) __half g_wl[64 * 256];

// ---------------- helpers ----------------------------------------------------
__device__ __forceinline__ uint32_t smem_u32(const void* p) {
    uint32_t a;
    asm("{ .reg .u64 t; cvta.to.shared.u64 t, %1; cvt.u32.u64 %0, t; }" : "=r"(a) : "l"(p));
    return a;
}
#define SW128(o) ((o) ^ (((o) >> 3) & 0x70))

__device__ __forceinline__ void ldm_x4(uint32_t* r, uint32_t addr) {
    asm volatile("ldmatrix.sync.aligned.m8n8.x4.shared.b16 {%0,%1,%2,%3}, [%4];"
                 : "=r"(r[0]), "=r"(r[1]), "=r"(r[2]), "=r"(r[3]) : "r"(addr));
}
__device__ __forceinline__ void mma_f16(float* c, const uint32_t* a, uint32_t b0, uint32_t b1) {
    asm volatile(
        "mma.sync.aligned.m16n8k16.row.col.f32.f16.f16.f32 "
        "{%0,%1,%2,%3}, {%4,%5,%6,%7}, {%8,%9}, {%0,%1,%2,%3};"
        : "+f"(c[0]), "+f"(c[1]), "+f"(c[2]), "+f"(c[3])
        : "r"(a[0]), "r"(a[1]), "r"(a[2]), "r"(a[3]), "r"(b0), "r"(b1));
}
__device__ __forceinline__ void cp16(uint32_t dst, const void* src) {
    asm volatile("cp.async.cg.shared.global [%0], [%1], 16;" :: "r"(dst), "l"(src));
}
#define CP_COMMIT() asm volatile("cp.async.commit_group;" ::: "memory")
#define CP_WAIT0()  asm volatile("cp.async.wait_group 0;" ::: "memory")

// ---------------- prep: weight convert + degree count + stats/flag zero -----
#define CVT_TOTAL (32768 + 196608 + 16384)
__global__ void prep_kernel(const float* __restrict__ W0,
                            const float* __restrict__ Wh,
                            const float* __restrict__ Wl,
                            const int* __restrict__ rowE) {
    cudaGridDependencySynchronize();
    int i = blockIdx.x * 256 + threadIdx.x;
    if (i < NE) atomicAdd(&g_deg[rowE[i]], 1);
    if (i < 1024) { g_sumA[i] = 0.f; g_sumsqA[i] = 0.f; }
    if (i < SCAN_BLOCKS) g_scanFlag[i] = 0;
    if (i < 32768) {
        int n = i >> 7, k = i & 127;
        g_w0[i] = __float2half_rn(W0[k * 256 + n]);
    } else if (i < 229376) {
        int j = i - 32768;
        int l = j >> 16, r = j & 65535;
        int n = r >> 8, k = r & 255;
        g_wh[j] = __float2half_rn(Wh[l * 65536 + k * 256 + n]);
    } else if (i < CVT_TOTAL) {
        int j = i - 229376;
        int n = j >> 8, k = j & 255;
        g_wl[j] = __float2half_rn((n < D_O) ? Wl[k * D_O + n] : 0.f);
    }
}

// ---------------- single-kernel scan (all blocks co-resident) ---------------
__global__ __launch_bounds__(1024)
void scan_kernel() {
    __shared__ int sm[1024];
    __shared__ int wsum[32];
    __shared__ int s_prev;
    int tid = threadIdx.x, b = blockIdx.x;
    cudaGridDependencySynchronize();
    int i = b * 1024 + tid;
    int v = (i < NN) ? g_deg[i] : 0;
    int x = v;
    sm[tid] = x;
    __syncthreads();
    #pragma unroll
    for (int off = 1; off < 1024; off <<= 1) {
        int t = (tid >= off) ? sm[tid - off] : 0;
        __syncthreads();
        x += t;
        sm[tid] = x;
        __syncthreads();
    }
    if (tid == 1023) {
        g_scanAgg[b] = x;
        __threadfence();
        atomicExch(&g_scanFlag[b], 1);
    }
    int myv = 0;
    if (tid < b) {
        while (atomicAdd(&g_scanFlag[tid], 0) == 0) {}
        myv = __ldcg(&g_scanAgg[tid]);
    }
    #pragma unroll
    for (int off = 16; off > 0; off >>= 1)
        myv += __shfl_xor_sync(0xffffffffu, myv, off);
    if ((tid & 31) == 0) wsum[tid >> 5] = myv;
    __syncthreads();
    if (tid < 32) {
        int sv = wsum[tid];
        #pragma unroll
        for (int off = 16; off > 0; off >>= 1)
            sv += __shfl_xor_sync(0xffffffffu, sv, off);
        if (tid == 0) s_prev = sv;
    }
    __syncthreads();
    int prev = s_prev;
    if (i < NN) {
        int rp = prev + x - v;
        g_rowptr[i] = rp;
        g_cursor[i] = rp;
        g_dinv[i] = rsqrtf((float)(v + 1));
    }
    if (b == SCAN_BLOCKS - 1 && tid == 1023) g_rowptr[NN] = prev + x;
}

// ---------------- CSR fill + x->fp16*dinv + deg reset (one launch) ----------
__global__ void csr_x_kernel(const int* __restrict__ rowE, const int* __restrict__ colE,
                             const float* __restrict__ x, __half* __restrict__ xh) {
    cudaGridDependencySynchronize();
    int i = blockIdx.x * 256 + threadIdx.x;
    if (i < NE) {
        int p = atomicAdd(&g_cursor[rowE[i]], 1);
        g_col[p] = colE[i];
    }
    if (i < NN) g_deg[i] = 0;
    if (i < NN * 32) {
        int row = i >> 5;
        float d = g_dinv[row];
        float4 v = reinterpret_cast<const float4*>(x)[i];
        __half2 a = __floats2half2_rn(v.x * d, v.y * d);
        __half2 b = __floats2half2_rn(v.z * d, v.w * d);
        uint2 u;
        u.x = *reinterpret_cast<uint32_t*>(&a);
        u.y = *reinterpret_cast<uint32_t*>(&b);
        reinterpret_cast<uint2*>(xh)[i] = u;
    }
}

// ---------------- pipelined warp-MMA single-product fp16 GEMM (PDL) ---------
template <int KTOT, int NT, bool BN, bool SCALE, bool STATS>
__global__ __launch_bounds__(512)
void gemm_mma_kernel(const __half* __restrict__ A,
                     const __half* __restrict__ W,
                     __half* __restrict__ C,
                     const float* __restrict__ statsS,
                     const float* __restrict__ statsQ,
                     const float* __restrict__ gamma,
                     const float* __restrict__ beta,
                     float* __restrict__ outS,
                     float* __restrict__ outQ) {
    constexpr int OF_B = 16384;               // A: 128 rows x 128B
    constexpr int STG = 16384 + NT * 128;
    constexpr int NPW = NT / 4;
    constexpr int NI = NPW / 8;
    constexpr int KCH = KTOT / 64;

    extern __shared__ __align__(1024) char smem[];
    __shared__ float s_scale[256];
    __shared__ float s_shift[256];
    uint32_t sb = smem_u32(smem);
    int tid = threadIdx.x, lane = tid & 31, wid = tid >> 5;
    int wm = wid >> 2, wn = wid & 3;
    int rowBase = blockIdx.x * 128;

    int cg = (tid & 7) * 8;
    int rr = tid >> 3;
    uint4 av[2];

    auto cpB = [&](int ch, int s) {
        int k0 = ch * 64;
        uint32_t base = sb + s * STG;
        #pragma unroll
        for (int p = 0; p < NT / 64; ++p) {
            int n = rr + p * 64;
            size_t go = (size_t)n * KTOT + k0 + cg;
            uint32_t off = SW128((uint32_t)(n * 128 + cg * 2));
            cp16(base + OF_B + off, W + go);
        }
    };

    cpB(0, 0);
    cudaGridDependencySynchronize();

    if (BN) {
        if (tid < 256) {
            float s = statsS[tid];
            float q = statsQ[tid];
            float mu = s * (1.f / NN);
            float var = q * (1.f / NN) - mu * mu;
            float sc = rsqrtf(var + 1e-5f) * gamma[tid];
            s_scale[tid] = sc;
            s_shift[tid] = beta[tid] - mu * sc;
        }
        __syncthreads();
    }

    float acc[2][NI][4];
    #pragma unroll
    for (int mi = 0; mi < 2; ++mi)
        #pragma unroll
        for (int ni = 0; ni < NI; ++ni)
            #pragma unroll
            for (int q = 0; q < 4; ++q) acc[mi][ni][q] = 0.f;

    auto ldgA = [&](int ch) {
        int k0 = ch * 64;
        #pragma unroll
        for (int p = 0; p < 2; ++p) {
            int gr = rowBase + rr + p * 64;
            if (gr < NN)
                av[p] = *reinterpret_cast<const uint4*>(A + (size_t)gr * KTOT + k0 + cg);
            else
                av[p] = make_uint4(0, 0, 0, 0);
        }
    };
    auto stsA = [&](int ch, int s) {
        int k0 = ch * 64;
        char* base = smem + s * STG;
        #pragma unroll
        for (int p = 0; p < 2; ++p) {
            __half2* hp = reinterpret_cast<__half2*>(&av[p]);
            uint4 o;
            __half2* op = reinterpret_cast<__half2*>(&o);
            #pragma unroll
            for (int j = 0; j < 4; ++j) {
                float2 f = __half22float2(hp[j]);
                int c = k0 + cg + j * 2;
                f.x = fmaxf(fmaf(f.x, s_scale[c], s_shift[c]), 0.f);
                f.y = fmaxf(fmaf(f.y, s_scale[c + 1], s_shift[c + 1]), 0.f);
                op[j] = __floats2half2_rn(f.x, f.y);
            }
            uint32_t off = SW128((uint32_t)((rr + p * 64) * 128 + cg * 2));
            *reinterpret_cast<uint4*>(base + off) = o;
        }
    };
    auto cpA = [&](int ch, int s) {
        int k0 = ch * 64;
        uint32_t base = sb + s * STG;
        #pragma unroll
        for (int p = 0; p < 2; ++p) {
            int gr = rowBase + rr + p * 64;
            uint32_t off = SW128((uint32_t)((rr + p * 64) * 128 + cg * 2));
            if (gr < NN)
                cp16(base + off, A + (size_t)gr * KTOT + k0 + cg);
            else
                *reinterpret_cast<uint4*>(smem + s * STG + off) = make_uint4(0, 0, 0, 0);
        }
    };
    auto domma = [&](int s) {
        uint32_t aF = sb + s * STG;
        uint32_t bF = aF + OF_B;
        #pragma unroll
        for (int ks = 0; ks < 4; ++ks) {
            int kk = ks * 16;
            uint32_t af[2][4];
            #pragma unroll
            for (int mi = 0; mi < 2; ++mi) {
                int r = wm * 32 + mi * 16 + (lane & 15);
                int c = kk + (lane >> 4) * 8;
                uint32_t off = SW128((uint32_t)(r * 128 + c * 2));
                ldm_x4(af[mi], aF + off);
            }
            #pragma unroll
            for (int nt = 0; nt < NI / 2; ++nt) {
                int g = lane >> 3;
                int row = wn * NPW + nt * 16 + (g >> 1) * 8 + (lane & 7);
                int c = kk + (g & 1) * 8;
                uint32_t off = SW128((uint32_t)(row * 128 + c * 2));
                uint32_t bh[4];
                ldm_x4(bh, bF + off);
                #pragma unroll
                for (int half = 0; half < 2; ++half) {
                    int ni = nt * 2 + half;
                    #pragma unroll
                    for (int mi = 0; mi < 2; ++mi)
                        mma_f16(acc[mi][ni], af[mi], bh[half * 2], bh[half * 2 + 1]);
                }
            }
        }
    };

    if (BN) ldgA(0); else cpA(0, 0);
    CP_COMMIT();
    if (BN) stsA(0, 0);

    for (int ch = 0; ch < KCH; ++ch) {
        int s = ch & 1;
        CP_WAIT0();
        __syncthreads();
        if (ch + 1 < KCH) {
            if (BN) ldgA(ch + 1); else cpA(ch + 1, s ^ 1);
            cpB(ch + 1, s ^ 1);
            CP_COMMIT();
        }
        domma(s);
        if (BN && ch + 1 < KCH) stsA(ch + 1, s ^ 1);
    }

    // epilogue: fp16 store (x dinv if SCALE)
    #pragma unroll
    for (int mi = 0; mi < 2; ++mi) {
        int r0 = rowBase + wm * 32 + mi * 16 + (lane >> 2);
        int r1 = r0 + 8;
        float d0 = 1.f, d1 = 1.f;
        if (SCALE) {
            d0 = (r0 < NN) ? g_dinv[r0] : 0.f;
            d1 = (r1 < NN) ? g_dinv[r1] : 0.f;
        }
        #pragma unroll
        for (int ni = 0; ni < NI; ++ni) {
            int c0 = wn * NPW + ni * 8 + (lane & 3) * 2;
            if (r0 < NN)
                *reinterpret_cast<__half2*>(C + (size_t)r0 * NT + c0) =
                    __floats2half2_rn(acc[mi][ni][0] * d0, acc[mi][ni][1] * d0);
            if (r1 < NN)
                *reinterpret_cast<__half2*>(C + (size_t)r1 * NT + c0) =
                    __floats2half2_rn(acc[mi][ni][2] * d1, acc[mi][ni][3] * d1);
        }
    }

    // fused BN stats (layer-0 GEMM): fp32 accumulators, padding rows are zero
    if constexpr (STATS) {
        __shared__ float s_sum[256];
        __shared__ float s_sq[256];
        if (tid < 256) { s_sum[tid] = 0.f; s_sq[tid] = 0.f; }
        __syncthreads();
        #pragma unroll
        for (int ni = 0; ni < NI; ++ni) {
            float s0 = 0.f, q0 = 0.f, s1 = 0.f, q1 = 0.f;
            #pragma unroll
            for (int mi = 0; mi < 2; ++mi) {
                float va = acc[mi][ni][0], vb = acc[mi][ni][2];
                s0 += va + vb; q0 += va * va + vb * vb;
                float vc = acc[mi][ni][1], vd = acc[mi][ni][3];
                s1 += vc + vd; q1 += vc * vc + vd * vd;
            }
            #pragma unroll
            for (int off = 4; off <= 16; off <<= 1) {
                s0 += __shfl_xor_sync(0xffffffffu, s0, off);
                q0 += __shfl_xor_sync(0xffffffffu, q0, off);
                s1 += __shfl_xor_sync(0xffffffffu, s1, off);
                q1 += __shfl_xor_sync(0xffffffffu, q1, off);
            }
            if ((lane >> 2) == 0) {
                int c0 = wn * NPW + ni * 8 + (lane & 3) * 2;
                atomicAdd(&s_sum[c0], s0);
                atomicAdd(&s_sq[c0], q0);
                atomicAdd(&s_sum[c0 + 1], s1);
                atomicAdd(&s_sq[c0 + 1], q1);
            }
        }
        __syncthreads();
        if (tid < 256) {
            atomicAdd(&outS[tid], s_sum[tid]);
            atomicAdd(&outQ[tid], s_sq[tid]);
        }
    }
}

// ---------------- SpMM fp16 -> fp16, HADD2 accumulation, PDL ----------------
// Inner loop: pure half2 adds (no conversion). Epilogue: fp32 for dinv+stats.
template <bool STATS, int COLS>
__global__ __launch_bounds__(512)
void spmmh_kernel(const __half* __restrict__ in, __half* __restrict__ out,
                  float* __restrict__ outS, float* __restrict__ outQ) {
    constexpr int CPL = COLS / 32;       // halves per lane (4 or 8)
    constexpr int H2 = CPL / 2;          // half2 regs (2 or 4)
    int warp = threadIdx.x >> 5, lane = threadIdx.x & 31;
    int row = blockIdx.x * 16 + warp;

    int s = g_rowptr[row], e = g_rowptr[row + 1];
    float d = g_dinv[row];
    cudaGridDependencySynchronize();

    __half2 hacc[H2];
    {
        const __half2* p = reinterpret_cast<const __half2*>(in + (size_t)row * COLS + lane * CPL);
        #pragma unroll
        for (int j = 0; j < H2; ++j) hacc[j] = p[j];
    }
    for (int i = s; i < e; ++i) {
        int c = g_col[i];
        const __half* p = in + (size_t)c * COLS + lane * CPL;
        if constexpr (H2 == 4) {
            uint4 u = *reinterpret_cast<const uint4*>(p);
            __half2* hp = reinterpret_cast<__half2*>(&u);
            #pragma unroll
            for (int j = 0; j < 4; ++j) hacc[j] = __hadd2(hacc[j], hp[j]);
        } else {
            uint2 u = *reinterpret_cast<const uint2*>(p);
            __half2* hp = reinterpret_cast<__half2*>(&u);
            #pragma unroll
            for (int j = 0; j < 2; ++j) hacc[j] = __hadd2(hacc[j], hp[j]);
        }
    }

    // epilogue: fp32 scale + store + stats
    float acc[CPL];
    #pragma unroll
    for (int j = 0; j < H2; ++j) {
        float2 f = __half22float2(hacc[j]);
        acc[j * 2] = f.x * d;
        acc[j * 2 + 1] = f.y * d;
    }
    {
        __half2 o[H2];
        #pragma unroll
        for (int j = 0; j < H2; ++j)
            o[j] = __floats2half2_rn(acc[j * 2], acc[j * 2 + 1]);
        __half* op = out + (size_t)row * COLS + lane * CPL;
        if constexpr (H2 == 4)
            *reinterpret_cast<uint4*>(op) = *reinterpret_cast<uint4*>(o);
        else
            *reinterpret_cast<uint2*>(op) = *reinterpret_cast<uint2*>(o);
    }

    if constexpr (STATS) {
        __shared__ float ss[16][COLS];
        __shared__ float sq[16][COLS];
        #pragma unroll
        for (int j = 0; j < CPL; ++j) {
            ss[warp][lane * CPL + j] = acc[j];
            sq[warp][lane * CPL + j] = acc[j] * acc[j];
        }
        __syncthreads();
        int t = threadIdx.x;
        if (t < COLS) {
            float sm = 0.f;
            #pragma unroll
            for (int w = 0; w < 16; ++w) sm += ss[w][t];
            atomicAdd(&outS[t], sm);
        } else if (t < 2 * COLS) {
            int c = t - COLS;
            float sm = 0.f;
            #pragma unroll
            for (int w = 0; w < 16; ++w) sm += sq[w][c];
            atomicAdd(&outQ[c], sm);
        }
    }
}

// ---------------- final SpMM (64-stride fp16 in) + log_softmax, PDL ---------
__global__ __launch_bounds__(256)
void spmm40_softmax_kernel(const __half* __restrict__ hs,
                           const float* __restrict__ bl,
                           float* __restrict__ out) {
    int warp = threadIdx.x >> 5, lane = threadIdx.x & 31;
    int row = blockIdx.x * 8 + warp;
    int s = 0, e = 0;
    float d = 0.f;
    if (row < NN) {
        s = g_rowptr[row];
        e = g_rowptr[row + 1];
        d = g_dinv[row];
    }
    cudaGridDependencySynchronize();
    if (row >= NN) return;

    size_t rbase = (size_t)row * 64;
    float a0 = __half2float(hs[rbase + lane]);
    float a1 = (lane < 8) ? __half2float(hs[rbase + 32 + lane]) : 0.f;
    for (int i = s; i < e; ++i) {
        size_t cb = (size_t)g_col[i] * 64;
        a0 += __half2float(hs[cb + lane]);
        if (lane < 8) a1 += __half2float(hs[cb + 32 + lane]);
    }
    float v0 = fmaf(a0, d, bl[lane]);
    float v1 = (lane < 8) ? fmaf(a1, d, bl[32 + lane]) : 0.f;

    float m = v0;
    if (lane < 8) m = fmaxf(m, v1);
    #pragma unroll
    for (int off = 16; off > 0; off >>= 1)
        m = fmaxf(m, __shfl_xor_sync(0xffffffffu, m, off));
    float sum = __expf(v0 - m) + ((lane < 8) ? __expf(v1 - m) : 0.f);
    #pragma unroll
    for (int off = 16; off > 0; off >>= 1)
        sum += __shfl_xor_sync(0xffffffffu, sum, off);
    float lse = __logf(sum);
    size_t ob = (size_t)row * D_O;
    out[ob + lane] = v0 - m - lse;
    if (lane < 8) out[ob + 32 + lane] = v1 - m - lse;
}

// ---------------- PDL launch helper ------------------------------------------
template <typename F, typename... Args>
static void launchP(F* k, int grid, int block, size_t smem, Args... args) {
    cudaLaunchConfig_t cfg = {};
    cfg.gridDim = dim3(grid);
    cfg.blockDim = dim3(block);
    cfg.dynamicSmemBytes = smem;
    cfg.stream = 0;
    cudaLaunchAttribute at[1];
    at[0].id = cudaLaunchAttributeProgrammaticStreamSerialization;
    at[0].val.programmaticStreamSerializationAllowed = 1;
    cfg.attrs = at;
    cfg.numAttrs = 1;
    cudaLaunchKernelEx(&cfg, k, args...);
}

// ---------------- launcher ---------------------------------------------------
extern "C" void kernel_launch(void* const* d_in, const int* in_sizes, int n_in,
                              void* d_out, int out_size) {
    const float* x     = (const float*)d_in[0];
    const float* W0    = (const float*)d_in[1];
    const float* Wh    = (const float*)d_in[3];
    const float* gamma = (const float*)d_in[5];
    const float* beta  = (const float*)d_in[6];
    const float* Wl    = (const float*)d_in[7];
    const float* bl    = (const float*)d_in[8];
    const int*   ei    = (const int*)d_in[9];
    const int* rowE = ei;
    const int* colE = ei + NE;
    float* out = (float*)d_out;

    __half *pHA, *pHB, *w0, *wh, *wl;
    float *sumA, *sumsqA;
    cudaGetSymbolAddress((void**)&pHA, g_bufHA);
    cudaGetSymbolAddress((void**)&pHB, g_bufHB);
    cudaGetSymbolAddress((void**)&w0, g_w0);
    cudaGetSymbolAddress((void**)&wh, g_wh);
    cudaGetSymbolAddress((void**)&wl, g_wl);
    cudaGetSymbolAddress((void**)&sumA, g_sumA);
    cudaGetSymbolAddress((void**)&sumsqA, g_sumsqA);

    constexpr int SMEM256 = 2 * (16384 + 256 * 128);  // 98304
    constexpr int SMEM64  = 2 * (16384 + 64 * 128);   // 49152
    cudaFuncSetAttribute(gemm_mma_kernel<128, 256, false, false, true>,
                         cudaFuncAttributeMaxDynamicSharedMemorySize, SMEM256);
    cudaFuncSetAttribute(gemm_mma_kernel<256, 256, true, true, false>,
                         cudaFuncAttributeMaxDynamicSharedMemorySize, SMEM256);
    cudaFuncSetAttribute(gemm_mma_kernel<256, 64, true, true, false>,
                         cudaFuncAttributeMaxDynamicSharedMemorySize, SMEM64);

    const int EB = (NE + 255) / 256;       // 6250
    const int MT = (NN + 127) / 128;       // 782
    const int SPB = NN / 16;               // 6250
    const int XB = (NN * 32 + 255) / 256;  // 12500

    // prep chain (PDL; each syncs at top before touching dependent data)
    launchP(&prep_kernel, EB, 256, (size_t)0, W0, Wh, Wl, rowE);
    launchP(&scan_kernel, SCAN_BLOCKS, 1024, (size_t)0);
    launchP(&csr_x_kernel, XB, 256, (size_t)0, rowE, colE, x, (__half*)pHA);

    // layer 0
    launchP(&spmmh_kernel<false, 128>, SPB, 512, (size_t)0,
            (const __half*)pHA, (__half*)pHB, (float*)nullptr, (float*)nullptr);
    launchP(&gemm_mma_kernel<128, 256, false, false, true>, MT, 512, (size_t)SMEM256,
            (const __half*)pHB, (const __half*)w0, (__half*)pHA,
            (const float*)nullptr, (const float*)nullptr,
            (const float*)nullptr, (const float*)nullptr,
            (float*)sumA, (float*)sumsqA);

    // hidden layers 1..3
    for (int l = 0; l < 3; ++l) {
        launchP(&gemm_mma_kernel<256, 256, true, true, false>, MT, 512, (size_t)SMEM256,
                (const __half*)pHA, (const __half*)(wh + (size_t)l * 65536), (__half*)pHB,
                (const float*)(sumA + (size_t)l * 256), (const float*)(sumsqA + (size_t)l * 256),
                (const float*)(gamma + (size_t)l * 256), (const float*)(beta + (size_t)l * 256),
                (float*)nullptr, (float*)nullptr);
        launchP(&spmmh_kernel<true, 256>, SPB, 512, (size_t)0,
                (const __half*)pHB, (__half*)pHA,
                (float*)(sumA + (size_t)(l + 1) * 256),
                (float*)(sumsqA + (size_t)(l + 1) * 256));
    }

    // final layer + softmax
    launchP(&gemm_mma_kernel<256, 64, true, true, false>, MT, 512, (size_t)SMEM64,
            (const __half*)pHA, (const __half*)wl, (__half*)pHB,
            (const float*)(sumA + 3 * 256), (const float*)(sumsqA + 3 * 256),
            (const float*)(gamma + 3 * 256), (const float*)(beta + 3 * 256),
            (float*)nullptr, (float*)nullptr);
    launchP(&spmm40_softmax_kernel, NN / 8, 256, (size_t)0,
            (const __half*)pHB, (const float*)bl, (float*)out);
}